// round 9
// baseline (speedup 1.0000x reference)
#include <cuda_runtime.h>
#include <cuda_bf16.h>
#include <math.h>
#include <stdint.h>

#define Bv 2
#define Lv 2048
#define Tv 2048
#define Dv 1024
#define Hv 16
#define HDv 64
#define BHv (Bv*Hv)
typedef __nv_bfloat16 bf16;

// ---------------- scratch ----------------
__device__ bf16 g_xh[Bv*Lv*Dv], g_xl[Bv*Lv*Dv];
__device__ bf16 g_ch[Bv*Tv*Dv], g_cl[Bv*Tv*Dv];
__device__ bf16 g_Wqh[Dv*Dv],   g_Wql[Dv*Dv];        // [N][K]
__device__ bf16 g_Wkh[2*Dv*Dv], g_Wkl[2*Dv*Dv];
__device__ bf16 g_Wph[Dv*Dv],   g_Wpl[Dv*Dv];
__device__ bf16 g_Qh[BHv*Lv*HDv], g_Ql[BHv*Lv*HDv]; // [bh][l][hd] (scaled 0.125)
__device__ bf16 g_Kch[BHv*Tv*HDv], g_Kcl[BHv*Tv*HDv]; // compacted K [bh][j][hd]
__device__ bf16 g_Vh[BHv*Tv*HDv], g_Vl[BHv*Tv*HDv];
__device__ bf16 g_Vth[BHv*HDv*Tv], g_Vtl[BHv*HDv*Tv]; // compacted V^T [bh][hd][j]
__device__ bf16 g_Oh[Bv*Lv*Dv], g_Ol[Bv*Lv*Dv];     // [b*l][D]
__device__ int  g_vidx[Bv][Tv];
__device__ int  g_pos[Bv][Tv];   // dest idx or -1
__device__ int  g_nv[Bv];

// ---------------- helpers ----------------
__device__ __forceinline__ uint32_t smem_u32(const void* p){
    uint32_t a; asm("{ .reg .u64 t; cvta.to.shared.u64 t, %1; cvt.u32.u64 %0, t; }":"=r"(a):"l"(p)); return a;
}
__device__ __forceinline__ void cp16(uint32_t dst, const void* src){
    asm volatile("cp.async.cg.shared.global [%0], [%1], 16;" :: "r"(dst), "l"(src));
}
#define CP_COMMIT() asm volatile("cp.async.commit_group;")
#define CP_WAIT1()  asm volatile("cp.async.wait_group 1;")
#define CP_WAIT0()  asm volatile("cp.async.wait_group 0;")

__device__ __forceinline__ void ldsm4(unsigned r[4], uint32_t a){
    asm volatile("ldmatrix.sync.aligned.m8n8.x4.shared.b16 {%0,%1,%2,%3}, [%4];"
        : "=r"(r[0]), "=r"(r[1]), "=r"(r[2]), "=r"(r[3]) : "r"(a));
}
__device__ __forceinline__ void bsplit(float x, unsigned short &h, unsigned short &l){
    bf16 hb = __float2bfloat16_rn(x);
    bf16 lb = __float2bfloat16_rn(x - __bfloat162float(hb));
    h = __bfloat16_as_ushort(hb); l = __bfloat16_as_ushort(lb);
}
__device__ __forceinline__ void pksplit(float a, float b, unsigned &hi, unsigned &lo){
    unsigned short h0,l0,h1,l1; bsplit(a,h0,l0); bsplit(b,h1,l1);
    hi = (unsigned)h0 | ((unsigned)h1<<16); lo = (unsigned)l0 | ((unsigned)l1<<16);
}
__device__ __forceinline__ void mma_bf16(float c[4], const unsigned a[4], const unsigned b[2]){
    asm volatile("mma.sync.aligned.m16n8k16.row.col.f32.bf16.bf16.f32 "
        "{%0,%1,%2,%3}, {%4,%5,%6,%7}, {%8,%9}, {%0,%1,%2,%3};"
        : "+f"(c[0]), "+f"(c[1]), "+f"(c[2]), "+f"(c[3])
        : "r"(a[0]), "r"(a[1]), "r"(a[2]), "r"(a[3]), "r"(b[0]), "r"(b[1]));
}

// ---------------- prep kernels ----------------
__global__ void fsplit(const float* __restrict__ in, bf16* __restrict__ h, bf16* __restrict__ l, int n){
    int i = blockIdx.x*256 + threadIdx.x;
    if (i < n){ unsigned short a,b; bsplit(in[i],a,b); h[i]=__ushort_as_bfloat16(a); l[i]=__ushort_as_bfloat16(b); }
}
__global__ void wprep(const float* __restrict__ W, bf16* __restrict__ th, bf16* __restrict__ tl, int N){
    __shared__ float t[32][33];
    int k0 = blockIdx.y*32, n0 = blockIdx.x*32, tx = threadIdx.x, ty = threadIdx.y;
    #pragma unroll
    for (int j=0;j<4;j++) t[ty+j*8][tx] = W[(size_t)(k0+ty+j*8)*N + n0+tx];
    __syncthreads();
    #pragma unroll
    for (int j=0;j<4;j++){
        unsigned short h,l; bsplit(t[tx][ty+j*8], h, l);
        size_t o = (size_t)(n0+ty+j*8)*Dv + k0+tx;
        th[o]=__ushort_as_bfloat16(h); tl[o]=__ushort_as_bfloat16(l);
    }
}
// mask scan: valid-index list, dest map, count per batch
__global__ void mscan(const int* __restrict__ mask){
    __shared__ int ps[256];
    int b = blockIdx.x, tid = threadIdx.x;
    int v[8]; int cnt = 0;
    #pragma unroll
    for (int i=0;i<8;i++){ v[i] = (mask[b*Tv + tid*8 + i] != 0); cnt += v[i]; }
    ps[tid] = cnt; __syncthreads();
    for (int off=1; off<256; off<<=1){
        int x = (tid >= off) ? ps[tid-off] : 0;
        __syncthreads();
        ps[tid] += x;
        __syncthreads();
    }
    int pre = ps[tid] - cnt;
    #pragma unroll
    for (int i=0;i<8;i++){
        int t = tid*8 + i;
        if (v[i]){ g_vidx[b][pre] = t; g_pos[b][t] = pre; pre++; }
        else g_pos[b][t] = -1;
    }
    if (tid == 255) g_nv[b] = ps[255];
}
// gather + transpose V planes into compacted [bh][hd][j] (zero tail)
__global__ void vtgather(){
    __shared__ bf16 t[32][33];
    int bh = blockIdx.z, b = bh>>4;
    int j0 = blockIdx.x*32, hd0 = blockIdx.y*32;
    int tx = threadIdx.x, ty = threadIdx.y;
    int nv = g_nv[b];
    for (int plane=0; plane<2; plane++){
        const bf16* src = plane ? g_Vl : g_Vh;
        bf16* dst = plane ? g_Vtl : g_Vth;
        #pragma unroll
        for (int jj=0;jj<4;jj++){
            int j = j0 + ty + jj*8;
            bf16 val = __ushort_as_bfloat16((unsigned short)0);
            if (j < nv) val = src[((size_t)bh*Tv + g_vidx[b][j])*HDv + hd0+tx];
            t[ty+jj*8][tx] = val;
        }
        __syncthreads();
        #pragma unroll
        for (int jj=0;jj<4;jj++)
            dst[((size_t)bh*HDv + hd0+ty+jj*8)*Tv + j0+tx] = t[tx][ty+jj*8];
        __syncthreads();
    }
}

// ---------------- HMMA GEMM, cp.async 2-stage + ldmatrix ----------------
#define GLD 40
#define G_STG (4*128*GLD)
#define G_SMEM (2*G_STG*2)

__global__ __launch_bounds__(256,2) void hgemm(
    const bf16* __restrict__ Agh, const bf16* __restrict__ Agl,
    const bf16* __restrict__ Wgh, const bf16* __restrict__ Wgl,
    const float* __restrict__ bias, int mode, float* __restrict__ outf)
{
    extern __shared__ bf16 gsm[];
    const uint32_t sbase = smem_u32(gsm);
    const int tid = threadIdx.x, lane = tid&31, warp = tid>>5;
    const int g = lane>>2, tig = lane&3;
    const int wm = warp>>2, wn = warp&3;
    const int m0 = blockIdx.y*128, n0 = blockIdx.x*128;
    const int lrow = lane&7, ltile = lane>>3;
    const int rowA = (ltile&1)*8 + lrow, kA = (ltile>>1)*8;
    const int rowB = (ltile>>1)*8 + lrow, kB = (ltile&1)*8;

    float acc[4][4][4] = {};

    auto issue = [&](int buf, int k0){
        #pragma unroll
        for (int t=0;t<8;t++){
            int i = tid + t*256, plane = i>>9, w = i&511, row = w>>2, c4 = (w&3)*8;
            const bf16* src = plane==0?Agh : plane==1?Agl : plane==2?Wgh : Wgl;
            int grow = (plane<2?m0:n0) + row;
            cp16(sbase + (uint32_t)(buf*G_STG + plane*(128*GLD) + row*GLD + c4)*2,
                 src + (size_t)grow*1024 + k0 + c4);
        }
        CP_COMMIT();
    };

    issue(0, 0);
    for (int kb=0; kb<32; kb++){
        if (kb < 31) issue((kb+1)&1, (kb+1)*32);
        if (kb < 31) CP_WAIT1(); else CP_WAIT0();
        __syncthreads();
        const uint32_t aB = sbase + (uint32_t)((kb&1)*G_STG)*2;
        const uint32_t bB = aB + 2*128*GLD*2;
        #pragma unroll
        for (int ks=0; ks<2; ks++){
            unsigned ah[4][4], al[4][4], bh[4][2], bl[4][2];
            #pragma unroll
            for (int mt=0;mt<4;mt++){
                uint32_t off = (uint32_t)((wm*64 + mt*16 + rowA)*GLD + ks*16 + kA)*2;
                ldsm4(ah[mt], aB + off);
                ldsm4(al[mt], aB + 128*GLD*2 + off);
            }
            #pragma unroll
            for (int p2=0;p2<2;p2++){
                unsigned r4[4];
                uint32_t off = (uint32_t)((wn*32 + p2*16 + rowB)*GLD + ks*16 + kB)*2;
                ldsm4(r4, bB + off);
                bh[2*p2][0]=r4[0]; bh[2*p2][1]=r4[1]; bh[2*p2+1][0]=r4[2]; bh[2*p2+1][1]=r4[3];
                ldsm4(r4, bB + 128*GLD*2 + off);
                bl[2*p2][0]=r4[0]; bl[2*p2][1]=r4[1]; bl[2*p2+1][0]=r4[2]; bl[2*p2+1][1]=r4[3];
            }
            #pragma unroll
            for (int mt=0;mt<4;mt++)
                #pragma unroll
                for (int nt=0;nt<4;nt++){
                    mma_bf16(acc[mt][nt], ah[mt], bh[nt]);
                    mma_bf16(acc[mt][nt], ah[mt], bl[nt]);
                    mma_bf16(acc[mt][nt], al[mt], bh[nt]);
                }
        }
        __syncthreads();
    }

    #pragma unroll
    for (int mt=0;mt<4;mt++){
        #pragma unroll
        for (int nt=0;nt<4;nt++){
            int r = m0 + wm*64 + mt*16 + g;
            int c = n0 + wn*32 + nt*8 + 2*tig;
            float v00 = acc[mt][nt][0] + bias[c];
            float v01 = acc[mt][nt][1] + bias[c+1];
            float v10 = acc[mt][nt][2] + bias[c];
            float v11 = acc[mt][nt][3] + bias[c+1];
            if (mode == 0){
                *(float2*)(outf + (size_t)r*1024 + c)      = make_float2(v00, v01);
                *(float2*)(outf + (size_t)(r+8)*1024 + c)  = make_float2(v10, v11);
            } else {
                int n2 = c, half = 0;
                if (mode == 2 && c >= 1024){ n2 = c - 1024; half = 1; }
                int h = n2>>6, hd = n2&63;
                #pragma unroll
                for (int rr=0; rr<2; rr++){
                    int m = r + rr*8;
                    int b = m>>11, l = m&2047;
                    float sc = (mode==1) ? 0.125f : 1.0f;
                    unsigned hi, lo;
                    pksplit((rr?v10:v00)*sc, (rr?v11:v01)*sc, hi, lo);
                    if (mode == 1){
                        size_t base = ((size_t)(b*16 + h)*2048 + l)*64 + hd;
                        *(unsigned*)(g_Qh + base) = hi;
                        *(unsigned*)(g_Ql + base) = lo;
                    } else if (!half){
                        int dest = g_pos[b][l];               // compact K directly
                        if (dest >= 0){
                            size_t base = ((size_t)(b*16 + h)*2048 + dest)*64 + hd;
                            *(unsigned*)(g_Kch + base) = hi;
                            *(unsigned*)(g_Kcl + base) = lo;
                        }
                    } else {
                        size_t base = ((size_t)(b*16 + h)*2048 + l)*64 + hd;
                        *(unsigned*)(g_Vh + base) = hi;
                        *(unsigned*)(g_Vl + base) = lo;
                    }
                }
            }
        }
    }
}

// ---------------- HMMA flash attention (compacted KV, 128 q-rows/CTA) ----------------
#define ALD 72
#define QH_O 0
#define QL_O (128*ALD)
#define STG0 (2*128*ALD)
#define A_STG (4*64*ALD)
#define SM_ELEMS (STG0 + 2*A_STG)
#define ATT_SMEM (SM_ELEMS*2)

__global__ __launch_bounds__(256) void hattn()
{
    extern __shared__ bf16 sm[];
    const uint32_t sbase = smem_u32(sm);
    const int tid = threadIdx.x, lane = tid&31, warp = tid>>5;
    const int g = lane>>2, tig = lane&3;
    const int bh = blockIdx.y, b = bh>>4, h = bh&15, l0 = blockIdx.x*128;
    const int lrow = lane&7, ltile = lane>>3;
    const int rowA = (ltile&1)*8 + lrow, kA = (ltile>>1)*8;
    const int rowB = (ltile>>1)*8 + lrow, kB = (ltile&1)*8;
    const int nv = g_nv[b];
    const int nch = (nv + 63) >> 6;

    auto issueKV = [&](int buf, int t0){
        #pragma unroll
        for (int t=0;t<8;t++){
            int i = tid + t*256, plane = i>>9, w = i&511, row = w>>3, c8 = (w&7)*8;
            const bf16* gp;
            if (plane == 0)      gp = g_Kch + ((size_t)bh*Tv + t0 + row)*64 + c8;
            else if (plane == 1) gp = g_Kcl + ((size_t)bh*Tv + t0 + row)*64 + c8;
            else if (plane == 2) gp = g_Vth + ((size_t)bh*HDv + row)*Tv + t0 + c8;
            else                 gp = g_Vtl + ((size_t)bh*HDv + row)*Tv + t0 + c8;
            cp16(sbase + (uint32_t)(STG0 + buf*A_STG + plane*(64*ALD) + row*ALD + c8)*2, gp);
        }
        CP_COMMIT();
    };

    // Q planes [128][64] -> smem
    #pragma unroll
    for (int t=0;t<8;t++){
        int i = tid + t*256, plane = i>>10, w = i&1023, row = w>>3, c8 = (w&7)*8;
        const bf16* src = plane ? g_Ql : g_Qh;
        uint4 v = *(const uint4*)(src + ((size_t)bh*Lv + l0 + row)*64 + c8);
        *(uint4*)(sm + (plane?QL_O:QH_O) + row*ALD + c8) = v;
    }
    issueKV(0, 0);
    __syncthreads();

    unsigned qa[4][2][4];
    #pragma unroll
    for (int kk=0; kk<4; kk++)
        #pragma unroll
        for (int p=0; p<2; p++)
            ldsm4(qa[kk][p], sbase + (uint32_t)((p?QL_O:QH_O) + (warp*16 + rowA)*ALD + kk*16 + kA)*2);

    float mold[2] = {-INFINITY, -INFINITY};
    float lsum[2] = {0.f, 0.f};
    float o[8][4] = {};

    for (int ci=0; ci<nch; ci++){
        const int t0 = ci*64;
        if (ci < nch-1) issueKV((ci+1)&1, t0+64);
        if (ci < nch-1) CP_WAIT1(); else CP_WAIT0();
        __syncthreads();

        const uint32_t khB = sbase + (uint32_t)(STG0 + (ci&1)*A_STG)*2;
        const uint32_t klB = khB + 64*ALD*2;
        const uint32_t vhB = khB + 2*64*ALD*2;
        const uint32_t vlB = khB + 3*64*ALD*2;
        const int rem = nv - t0;

        float s[8][4] = {};
        #pragma unroll
        for (int kk=0; kk<4; kk++){
            unsigned bhf[8][2], blf[8][2];
            #pragma unroll
            for (int p2=0; p2<4; p2++){
                unsigned r4[4];
                uint32_t off = (uint32_t)((p2*16 + rowB)*ALD + kk*16 + kB)*2;
                ldsm4(r4, khB + off);
                bhf[2*p2][0]=r4[0]; bhf[2*p2][1]=r4[1]; bhf[2*p2+1][0]=r4[2]; bhf[2*p2+1][1]=r4[3];
                ldsm4(r4, klB + off);
                blf[2*p2][0]=r4[0]; blf[2*p2][1]=r4[1]; blf[2*p2+1][0]=r4[2]; blf[2*p2+1][1]=r4[3];
            }
            #pragma unroll
            for (int nt=0; nt<8; nt++){
                mma_bf16(s[nt], qa[kk][0], bhf[nt]);
                mma_bf16(s[nt], qa[kk][0], blf[nt]);
                mma_bf16(s[nt], qa[kk][1], bhf[nt]);
            }
        }

        float ma = mold[0], mb = mold[1];
        #pragma unroll
        for (int nt=0; nt<8; nt++){
            int c = nt*8 + 2*tig;
            if (c   >= rem){ s[nt][0] = -1e9f; s[nt][2] = -1e9f; }
            if (c+1 >= rem){ s[nt][1] = -1e9f; s[nt][3] = -1e9f; }
            ma = fmaxf(ma, fmaxf(s[nt][0], s[nt][1]));
            mb = fmaxf(mb, fmaxf(s[nt][2], s[nt][3]));
        }
        ma = fmaxf(ma, __shfl_xor_sync(0xffffffffu, ma, 1));
        ma = fmaxf(ma, __shfl_xor_sync(0xffffffffu, ma, 2));
        mb = fmaxf(mb, __shfl_xor_sync(0xffffffffu, mb, 1));
        mb = fmaxf(mb, __shfl_xor_sync(0xffffffffu, mb, 2));

        float aa = __expf(mold[0] - ma), ab = __expf(mold[1] - mb);
        float suma = 0.f, sumb = 0.f;
        #pragma unroll
        for (int nt=0; nt<8; nt++){
            s[nt][0] = __expf(s[nt][0] - ma);
            s[nt][1] = __expf(s[nt][1] - ma);
            s[nt][2] = __expf(s[nt][2] - mb);
            s[nt][3] = __expf(s[nt][3] - mb);
            suma += s[nt][0] + s[nt][1];
            sumb += s[nt][2] + s[nt][3];
        }
        suma += __shfl_xor_sync(0xffffffffu, suma, 1);
        suma += __shfl_xor_sync(0xffffffffu, suma, 2);
        sumb += __shfl_xor_sync(0xffffffffu, sumb, 1);
        sumb += __shfl_xor_sync(0xffffffffu, sumb, 2);
        lsum[0] = lsum[0]*aa + suma;  mold[0] = ma;
        lsum[1] = lsum[1]*ab + sumb;  mold[1] = mb;
        #pragma unroll
        for (int nt=0; nt<8; nt++){
            o[nt][0] *= aa; o[nt][1] *= aa; o[nt][2] *= ab; o[nt][3] *= ab;
        }

        #pragma unroll
        for (int kt=0; kt<4; kt++){
            unsigned pah[4], pal[4];
            pksplit(s[2*kt][0],   s[2*kt][1],   pah[0], pal[0]);
            pksplit(s[2*kt][2],   s[2*kt][3],   pah[1], pal[1]);
            pksplit(s[2*kt+1][0], s[2*kt+1][1], pah[2], pal[2]);
            pksplit(s[2*kt+1][2], s[2*kt+1][3], pah[3], pal[3]);
            #pragma unroll
            for (int p2=0; p2<4; p2++){
                unsigned rv[4], rl[4];
                uint32_t off = (uint32_t)((p2*16 + rowB)*ALD + kt*16 + kB)*2;
                ldsm4(rv, vhB + off);
                ldsm4(rl, vlB + off);
                unsigned v0h[2] = {rv[0], rv[1]}, v1h[2] = {rv[2], rv[3]};
                unsigned v0l[2] = {rl[0], rl[1]}, v1l[2] = {rl[2], rl[3]};
                mma_bf16(o[2*p2],   pah, v0h);
                mma_bf16(o[2*p2],   pah, v0l);
                mma_bf16(o[2*p2],   pal, v0h);
                mma_bf16(o[2*p2+1], pah, v1h);
                mma_bf16(o[2*p2+1], pah, v1l);
                mma_bf16(o[2*p2+1], pal, v1h);
            }
        }
        __syncthreads();
    }

    float inva = 1.0f / lsum[0], invb = 1.0f / lsum[1];
    int ra = l0 + warp*16 + g, rb = ra + 8;
    #pragma unroll
    for (int nt=0; nt<8; nt++){
        int c = h*64 + nt*8 + 2*tig;
        unsigned hi, lo;
        size_t basea = ((size_t)(b*Lv + ra))*Dv + c;
        pksplit(o[nt][0]*inva, o[nt][1]*inva, hi, lo);
        *(unsigned*)(g_Oh + basea) = hi;
        *(unsigned*)(g_Ol + basea) = lo;
        size_t baseb = ((size_t)(b*Lv + rb))*Dv + c;
        pksplit(o[nt][2]*invb, o[nt][3]*invb, hi, lo);
        *(unsigned*)(g_Oh + baseb) = hi;
        *(unsigned*)(g_Ol + baseb) = lo;
    }
}

// ---------------- launch ----------------
extern "C" void kernel_launch(void* const* d_in, const int* in_sizes, int n_in,
                              void* d_out, int out_size)
{
    const float* x     = (const float*)d_in[0];
    const float* ctx   = (const float*)d_in[1];
    const int*   cmsk  = (const int*)d_in[2];
    const float* Wq    = (const float*)d_in[3];
    const float* bq    = (const float*)d_in[4];
    const float* Wkv   = (const float*)d_in[5];
    const float* bkv   = (const float*)d_in[6];
    const float* Wproj = (const float*)d_in[7];
    const float* bproj = (const float*)d_in[8];
    float* out         = (float*)d_out;

    bf16 *xh,*xl,*ch,*cl,*wqh,*wql,*wkh,*wkl,*wph,*wpl,*oh,*ol;
    cudaGetSymbolAddress((void**)&xh, g_xh);   cudaGetSymbolAddress((void**)&xl, g_xl);
    cudaGetSymbolAddress((void**)&ch, g_ch);   cudaGetSymbolAddress((void**)&cl, g_cl);
    cudaGetSymbolAddress((void**)&wqh, g_Wqh); cudaGetSymbolAddress((void**)&wql, g_Wql);
    cudaGetSymbolAddress((void**)&wkh, g_Wkh); cudaGetSymbolAddress((void**)&wkl, g_Wkl);
    cudaGetSymbolAddress((void**)&wph, g_Wph); cudaGetSymbolAddress((void**)&wpl, g_Wpl);
    cudaGetSymbolAddress((void**)&oh, g_Oh);   cudaGetSymbolAddress((void**)&ol, g_Ol);

    cudaFuncSetAttribute(hgemm, cudaFuncAttributeMaxDynamicSharedMemorySize, G_SMEM);
    cudaFuncSetAttribute(hattn, cudaFuncAttributeMaxDynamicSharedMemorySize, ATT_SMEM);

    const int NM = Bv*Lv;  // 4096

    fsplit<<<NM*Dv/256, 256>>>(x, xh, xl, NM*Dv);                       // 0
    wprep<<<dim3(Dv/32, Dv/32), dim3(32,8)>>>(Wq, wqh, wql, Dv);        // 1
    fsplit<<<NM*Dv/256, 256>>>(ctx, ch, cl, NM*Dv);                     // 2
    hgemm<<<dim3(Dv/128, NM/128), 256, G_SMEM>>>(xh, xl, wqh, wql, bq, 1, nullptr);        // 3 (ncu slot)
    mscan<<<Bv, 256>>>(cmsk);                                           // 4
    wprep<<<dim3(2*Dv/32, Dv/32), dim3(32,8)>>>(Wkv, wkh, wkl, 2*Dv);   // 5
    hgemm<<<dim3(2*Dv/128, NM/128), 256, G_SMEM>>>(ch, cl, wkh, wkl, bkv, 2, nullptr);     // 6
    wprep<<<dim3(Dv/32, Dv/32), dim3(32,8)>>>(Wproj, wph, wpl, Dv);     // 7
    vtgather<<<dim3(Tv/32, HDv/32, BHv), dim3(32,8)>>>();               // 8
    hattn<<<dim3(Lv/128, BHv), 256, ATT_SMEM>>>();                      // 9
    hgemm<<<dim3(Dv/128, NM/128), 256, G_SMEM>>>(oh, ol, wph, wpl, bproj, 0, out);         // 10
}

// round 10
// speedup vs baseline: 1.2623x; 1.2623x over previous
#include <cuda_runtime.h>
#include <cuda_bf16.h>
#include <math.h>
#include <stdint.h>

#define Bv 2
#define Lv 2048
#define Tv 2048
#define Dv 1024
#define Hv 16
#define HDv 64
#define BHv (Bv*Hv)
typedef __nv_bfloat16 bf16;

// ---------------- scratch ----------------
__device__ bf16 g_xh[Bv*Lv*Dv], g_xl[Bv*Lv*Dv];
__device__ bf16 g_ch[Bv*Tv*Dv], g_cl[Bv*Tv*Dv];      // compacted ctx rows
__device__ bf16 g_Wqh[Dv*Dv],   g_Wql[Dv*Dv];        // [N][K]
__device__ bf16 g_Wkh[2*Dv*Dv], g_Wkl[2*Dv*Dv];
__device__ bf16 g_Wph[Dv*Dv],   g_Wpl[Dv*Dv];
__device__ bf16 g_Qh[BHv*Lv*HDv], g_Ql[BHv*Lv*HDv]; // [bh][l][hd] (scaled 0.125)
__device__ bf16 g_Kch[BHv*Tv*HDv], g_Kcl[BHv*Tv*HDv]; // compacted K [bh][j][hd]
__device__ bf16 g_Vh[BHv*Tv*HDv], g_Vl[BHv*Tv*HDv];   // compacted V [bh][j][hd]
__device__ bf16 g_Vth[BHv*HDv*Tv], g_Vtl[BHv*HDv*Tv]; // compacted V^T [bh][hd][j]
__device__ bf16 g_Oh[Bv*Lv*Dv], g_Ol[Bv*Lv*Dv];     // [b*l][D]
__device__ int  g_vidx[Bv][Tv];
__device__ int  g_nv[Bv];

// ---------------- helpers ----------------
__device__ __forceinline__ uint32_t smem_u32(const void* p){
    uint32_t a; asm("{ .reg .u64 t; cvta.to.shared.u64 t, %1; cvt.u32.u64 %0, t; }":"=r"(a):"l"(p)); return a;
}
__device__ __forceinline__ void cp16(uint32_t dst, const void* src){
    asm volatile("cp.async.cg.shared.global [%0], [%1], 16;" :: "r"(dst), "l"(src));
}
#define CP_COMMIT() asm volatile("cp.async.commit_group;")
#define CP_WAIT1()  asm volatile("cp.async.wait_group 1;")
#define CP_WAIT0()  asm volatile("cp.async.wait_group 0;")

__device__ __forceinline__ void ldsm4(unsigned r[4], uint32_t a){
    asm volatile("ldmatrix.sync.aligned.m8n8.x4.shared.b16 {%0,%1,%2,%3}, [%4];"
        : "=r"(r[0]), "=r"(r[1]), "=r"(r[2]), "=r"(r[3]) : "r"(a));
}
__device__ __forceinline__ void bsplit(float x, unsigned short &h, unsigned short &l){
    bf16 hb = __float2bfloat16_rn(x);
    bf16 lb = __float2bfloat16_rn(x - __bfloat162float(hb));
    h = __bfloat16_as_ushort(hb); l = __bfloat16_as_ushort(lb);
}
__device__ __forceinline__ void pksplit(float a, float b, unsigned &hi, unsigned &lo){
    unsigned short h0,l0,h1,l1; bsplit(a,h0,l0); bsplit(b,h1,l1);
    hi = (unsigned)h0 | ((unsigned)h1<<16); lo = (unsigned)l0 | ((unsigned)l1<<16);
}
__device__ __forceinline__ void mma_bf16(float c[4], const unsigned a[4], const unsigned b[2]){
    asm volatile("mma.sync.aligned.m16n8k16.row.col.f32.bf16.bf16.f32 "
        "{%0,%1,%2,%3}, {%4,%5,%6,%7}, {%8,%9}, {%0,%1,%2,%3};"
        : "+f"(c[0]), "+f"(c[1]), "+f"(c[2]), "+f"(c[3])
        : "r"(a[0]), "r"(a[1]), "r"(a[2]), "r"(a[3]), "r"(b[0]), "r"(b[1]));
}

// ---------------- prep kernels ----------------
__global__ void fsplit(const float* __restrict__ in, bf16* __restrict__ h, bf16* __restrict__ l, int n){
    int i = blockIdx.x*256 + threadIdx.x;
    if (i < n){ unsigned short a,b; bsplit(in[i],a,b); h[i]=__ushort_as_bfloat16(a); l[i]=__ushort_as_bfloat16(b); }
}
// gather valid ctx rows (compacted) and split
__global__ void csplit(const float* __restrict__ ctx){
    int row = blockIdx.x;
    int b = row >> 11, j = row & 2047;
    if (j >= g_nv[b]) return;
    const float* p = ctx + ((size_t)b*Tv + g_vidx[b][j])*Dv;
    size_t dst = ((size_t)b*Tv + j)*Dv;
    for (int c = threadIdx.x; c < Dv; c += 256){
        unsigned short h,l; bsplit(p[c], h, l);
        g_ch[dst + c] = __ushort_as_bfloat16(h);
        g_cl[dst + c] = __ushort_as_bfloat16(l);
    }
}
__global__ void wprep(const float* __restrict__ W, bf16* __restrict__ th, bf16* __restrict__ tl, int N){
    __shared__ float t[32][33];
    int k0 = blockIdx.y*32, n0 = blockIdx.x*32, tx = threadIdx.x, ty = threadIdx.y;
    #pragma unroll
    for (int j=0;j<4;j++) t[ty+j*8][tx] = W[(size_t)(k0+ty+j*8)*N + n0+tx];
    __syncthreads();
    #pragma unroll
    for (int j=0;j<4;j++){
        unsigned short h,l; bsplit(t[tx][ty+j*8], h, l);
        size_t o = (size_t)(n0+ty+j*8)*Dv + k0+tx;
        th[o]=__ushort_as_bfloat16(h); tl[o]=__ushort_as_bfloat16(l);
    }
}
// mask scan: valid-index list + count per batch
__global__ void mscan(const int* __restrict__ mask){
    __shared__ int ps[256];
    int b = blockIdx.x, tid = threadIdx.x;
    int v[8]; int cnt = 0;
    #pragma unroll
    for (int i=0;i<8;i++){ v[i] = (mask[b*Tv + tid*8 + i] != 0); cnt += v[i]; }
    ps[tid] = cnt; __syncthreads();
    for (int off=1; off<256; off<<=1){
        int x = (tid >= off) ? ps[tid-off] : 0;
        __syncthreads();
        ps[tid] += x;
        __syncthreads();
    }
    int pre = ps[tid] - cnt;
    #pragma unroll
    for (int i=0;i<8;i++){ if (v[i]) g_vidx[b][pre++] = tid*8 + i; }
    if (tid == 255) g_nv[b] = ps[255];
}
// transpose compacted V planes into [bh][hd][j] (zero tail)
__global__ void vtrans(){
    __shared__ bf16 t[32][33];
    int bh = blockIdx.z, b = bh>>4;
    int j0 = blockIdx.x*32, hd0 = blockIdx.y*32;
    int tx = threadIdx.x, ty = threadIdx.y;
    int nv = g_nv[b];
    for (int plane=0; plane<2; plane++){
        const bf16* src = plane ? g_Vl : g_Vh;
        bf16* dst = plane ? g_Vtl : g_Vth;
        #pragma unroll
        for (int jj=0;jj<4;jj++){
            int j = j0 + ty + jj*8;
            bf16 val = __ushort_as_bfloat16((unsigned short)0);
            if (j < nv) val = src[((size_t)bh*Tv + j)*HDv + hd0+tx];
            t[ty+jj*8][tx] = val;
        }
        __syncthreads();
        #pragma unroll
        for (int jj=0;jj<4;jj++)
            dst[((size_t)bh*HDv + hd0+ty+jj*8)*Tv + j0+tx] = t[tx][ty+jj*8];
        __syncthreads();
    }
}

// ---------------- HMMA GEMM, cp.async 2-stage + ldmatrix ----------------
#define GLD 40
#define G_STG (4*128*GLD)
#define G_SMEM (2*G_STG*2)

__global__ __launch_bounds__(256,2) void hgemm(
    const bf16* __restrict__ Agh, const bf16* __restrict__ Agl,
    const bf16* __restrict__ Wgh, const bf16* __restrict__ Wgl,
    const float* __restrict__ bias, int mode, float* __restrict__ outf)
{
    extern __shared__ bf16 gsm[];
    const uint32_t sbase = smem_u32(gsm);
    const int tid = threadIdx.x, lane = tid&31, warp = tid>>5;
    const int g = lane>>2, tig = lane&3;
    const int wm = warp>>2, wn = warp&3;
    const int m0 = blockIdx.y*128, n0 = blockIdx.x*128;
    // KV mode: skip tiles entirely beyond this batch's valid-row count
    if (mode == 2 && (m0 & 2047) >= g_nv[m0 >> 11]) return;
    const int lrow = lane&7, ltile = lane>>3;
    const int rowA = (ltile&1)*8 + lrow, kA = (ltile>>1)*8;
    const int rowB = (ltile>>1)*8 + lrow, kB = (ltile&1)*8;

    float acc[4][4][4] = {};

    auto issue = [&](int buf, int k0){
        #pragma unroll
        for (int t=0;t<8;t++){
            int i = tid + t*256, plane = i>>9, w = i&511, row = w>>2, c4 = (w&3)*8;
            const bf16* src = plane==0?Agh : plane==1?Agl : plane==2?Wgh : Wgl;
            int grow = (plane<2?m0:n0) + row;
            cp16(sbase + (uint32_t)(buf*G_STG + plane*(128*GLD) + row*GLD + c4)*2,
                 src + (size_t)grow*1024 + k0 + c4);
        }
        CP_COMMIT();
    };

    issue(0, 0);
    for (int kb=0; kb<32; kb++){
        if (kb < 31) issue((kb+1)&1, (kb+1)*32);
        if (kb < 31) CP_WAIT1(); else CP_WAIT0();
        __syncthreads();
        const uint32_t aB = sbase + (uint32_t)((kb&1)*G_STG)*2;
        const uint32_t bB = aB + 2*128*GLD*2;
        #pragma unroll
        for (int ks=0; ks<2; ks++){
            unsigned ah[4][4], al[4][4], bh[4][2], bl[4][2];
            #pragma unroll
            for (int mt=0;mt<4;mt++){
                uint32_t off = (uint32_t)((wm*64 + mt*16 + rowA)*GLD + ks*16 + kA)*2;
                ldsm4(ah[mt], aB + off);
                ldsm4(al[mt], aB + 128*GLD*2 + off);
            }
            #pragma unroll
            for (int p2=0;p2<2;p2++){
                unsigned r4[4];
                uint32_t off = (uint32_t)((wn*32 + p2*16 + rowB)*GLD + ks*16 + kB)*2;
                ldsm4(r4, bB + off);
                bh[2*p2][0]=r4[0]; bh[2*p2][1]=r4[1]; bh[2*p2+1][0]=r4[2]; bh[2*p2+1][1]=r4[3];
                ldsm4(r4, bB + 128*GLD*2 + off);
                bl[2*p2][0]=r4[0]; bl[2*p2][1]=r4[1]; bl[2*p2+1][0]=r4[2]; bl[2*p2+1][1]=r4[3];
            }
            #pragma unroll
            for (int mt=0;mt<4;mt++)
                #pragma unroll
                for (int nt=0;nt<4;nt++){
                    mma_bf16(acc[mt][nt], ah[mt], bh[nt]);
                    mma_bf16(acc[mt][nt], ah[mt], bl[nt]);
                    mma_bf16(acc[mt][nt], al[mt], bh[nt]);
                }
        }
        __syncthreads();
    }

    #pragma unroll
    for (int mt=0;mt<4;mt++){
        #pragma unroll
        for (int nt=0;nt<4;nt++){
            int r = m0 + wm*64 + mt*16 + g;
            int c = n0 + wn*32 + nt*8 + 2*tig;
            float v00 = acc[mt][nt][0] + bias[c];
            float v01 = acc[mt][nt][1] + bias[c+1];
            float v10 = acc[mt][nt][2] + bias[c];
            float v11 = acc[mt][nt][3] + bias[c+1];
            if (mode == 0){
                *(float2*)(outf + (size_t)r*1024 + c)      = make_float2(v00, v01);
                *(float2*)(outf + (size_t)(r+8)*1024 + c)  = make_float2(v10, v11);
            } else {
                int n2 = c, half = 0;
                if (mode == 2 && c >= 1024){ n2 = c - 1024; half = 1; }
                int h = n2>>6, hd = n2&63;
                #pragma unroll
                for (int rr=0; rr<2; rr++){
                    int m = r + rr*8;
                    int b = m>>11, l = m&2047;
                    float sc = (mode==1) ? 0.125f : 1.0f;
                    unsigned hi, lo;
                    pksplit((rr?v10:v00)*sc, (rr?v11:v01)*sc, hi, lo);
                    size_t base = ((size_t)(b*16 + h)*2048 + l)*64 + hd;
                    if (mode == 1){
                        *(unsigned*)(g_Qh + base) = hi;
                        *(unsigned*)(g_Ql + base) = lo;
                    } else if (!half){      // rows already compacted
                        *(unsigned*)(g_Kch + base) = hi;
                        *(unsigned*)(g_Kcl + base) = lo;
                    } else {
                        *(unsigned*)(g_Vh + base) = hi;
                        *(unsigned*)(g_Vl + base) = lo;
                    }
                }
            }
        }
    }
}

// ---------------- HMMA flash attention (compacted KV, 64 q-rows/CTA) ----------------
#define ALD 72
#define QH_O 0
#define QL_O (64*ALD)
#define STG0 (2*64*ALD)
#define A_STG (4*64*ALD)
#define SM_ELEMS (STG0 + 2*A_STG)
#define ATT_SMEM (SM_ELEMS*2)

__global__ __launch_bounds__(128) void hattn()
{
    extern __shared__ bf16 sm[];
    const uint32_t sbase = smem_u32(sm);
    const int tid = threadIdx.x, lane = tid&31, warp = tid>>5;
    const int g = lane>>2, tig = lane&3;
    const int bh = blockIdx.y, b = bh>>4, h = bh&15, l0 = blockIdx.x*64;
    const int lrow = lane&7, ltile = lane>>3;
    const int rowA = (ltile&1)*8 + lrow, kA = (ltile>>1)*8;
    const int rowB = (ltile>>1)*8 + lrow, kB = (ltile&1)*8;
    const int nv = g_nv[b];
    const int nch = (nv + 63) >> 6;

    auto issueKV = [&](int buf, int t0){
        #pragma unroll
        for (int t=0;t<16;t++){
            int i = tid + t*128, plane = i>>9, w = i&511, row = w>>3, c8 = (w&7)*8;
            const bf16* gp;
            if (plane == 0)      gp = g_Kch + ((size_t)bh*Tv + t0 + row)*64 + c8;
            else if (plane == 1) gp = g_Kcl + ((size_t)bh*Tv + t0 + row)*64 + c8;
            else if (plane == 2) gp = g_Vth + ((size_t)bh*HDv + row)*Tv + t0 + c8;
            else                 gp = g_Vtl + ((size_t)bh*HDv + row)*Tv + t0 + c8;
            cp16(sbase + (uint32_t)(STG0 + buf*A_STG + plane*(64*ALD) + row*ALD + c8)*2, gp);
        }
        CP_COMMIT();
    };

    #pragma unroll
    for (int t=0;t<8;t++){
        int i = tid + t*128, plane = i>>9, w = i&511, row = w>>3, c8 = (w&7)*8;
        const bf16* src = plane ? g_Ql : g_Qh;
        uint4 v = *(const uint4*)(src + ((size_t)bh*Lv + l0 + row)*64 + c8);
        *(uint4*)(sm + (plane?QL_O:QH_O) + row*ALD + c8) = v;
    }
    issueKV(0, 0);
    __syncthreads();

    unsigned qa[4][2][4];
    #pragma unroll
    for (int kk=0; kk<4; kk++)
        #pragma unroll
        for (int p=0; p<2; p++)
            ldsm4(qa[kk][p], sbase + (uint32_t)((p?QL_O:QH_O) + (warp*16 + rowA)*ALD + kk*16 + kA)*2);

    float mold[2] = {-INFINITY, -INFINITY};
    float lsum[2] = {0.f, 0.f};
    float o[8][4] = {};

    for (int ci=0; ci<nch; ci++){
        const int t0 = ci*64;
        if (ci < nch-1) issueKV((ci+1)&1, t0+64);
        if (ci < nch-1) CP_WAIT1(); else CP_WAIT0();
        __syncthreads();

        const uint32_t khB = sbase + (uint32_t)(STG0 + (ci&1)*A_STG)*2;
        const uint32_t klB = khB + 64*ALD*2;
        const uint32_t vhB = khB + 2*64*ALD*2;
        const uint32_t vlB = khB + 3*64*ALD*2;
        const int rem = nv - t0;

        float s[8][4] = {};
        #pragma unroll
        for (int kk=0; kk<4; kk++){
            unsigned bhf[8][2], blf[8][2];
            #pragma unroll
            for (int p2=0; p2<4; p2++){
                unsigned r4[4];
                uint32_t off = (uint32_t)((p2*16 + rowB)*ALD + kk*16 + kB)*2;
                ldsm4(r4, khB + off);
                bhf[2*p2][0]=r4[0]; bhf[2*p2][1]=r4[1]; bhf[2*p2+1][0]=r4[2]; bhf[2*p2+1][1]=r4[3];
                ldsm4(r4, klB + off);
                blf[2*p2][0]=r4[0]; blf[2*p2][1]=r4[1]; blf[2*p2+1][0]=r4[2]; blf[2*p2+1][1]=r4[3];
            }
            #pragma unroll
            for (int nt=0; nt<8; nt++){
                mma_bf16(s[nt], qa[kk][0], bhf[nt]);
                mma_bf16(s[nt], qa[kk][0], blf[nt]);
                mma_bf16(s[nt], qa[kk][1], bhf[nt]);
            }
        }

        float ma = mold[0], mb = mold[1];
        #pragma unroll
        for (int nt=0; nt<8; nt++){
            int c = nt*8 + 2*tig;
            if (c   >= rem){ s[nt][0] = -1e9f; s[nt][2] = -1e9f; }
            if (c+1 >= rem){ s[nt][1] = -1e9f; s[nt][3] = -1e9f; }
            ma = fmaxf(ma, fmaxf(s[nt][0], s[nt][1]));
            mb = fmaxf(mb, fmaxf(s[nt][2], s[nt][3]));
        }
        ma = fmaxf(ma, __shfl_xor_sync(0xffffffffu, ma, 1));
        ma = fmaxf(ma, __shfl_xor_sync(0xffffffffu, ma, 2));
        mb = fmaxf(mb, __shfl_xor_sync(0xffffffffu, mb, 1));
        mb = fmaxf(mb, __shfl_xor_sync(0xffffffffu, mb, 2));

        float aa = __expf(mold[0] - ma), ab = __expf(mold[1] - mb);
        float suma = 0.f, sumb = 0.f;
        #pragma unroll
        for (int nt=0; nt<8; nt++){
            s[nt][0] = __expf(s[nt][0] - ma);
            s[nt][1] = __expf(s[nt][1] - ma);
            s[nt][2] = __expf(s[nt][2] - mb);
            s[nt][3] = __expf(s[nt][3] - mb);
            suma += s[nt][0] + s[nt][1];
            sumb += s[nt][2] + s[nt][3];
        }
        suma += __shfl_xor_sync(0xffffffffu, suma, 1);
        suma += __shfl_xor_sync(0xffffffffu, suma, 2);
        sumb += __shfl_xor_sync(0xffffffffu, sumb, 1);
        sumb += __shfl_xor_sync(0xffffffffu, sumb, 2);
        lsum[0] = lsum[0]*aa + suma;  mold[0] = ma;
        lsum[1] = lsum[1]*ab + sumb;  mold[1] = mb;
        #pragma unroll
        for (int nt=0; nt<8; nt++){
            o[nt][0] *= aa; o[nt][1] *= aa; o[nt][2] *= ab; o[nt][3] *= ab;
        }

        #pragma unroll
        for (int kt=0; kt<4; kt++){
            unsigned pah[4], pal[4];
            pksplit(s[2*kt][0],   s[2*kt][1],   pah[0], pal[0]);
            pksplit(s[2*kt][2],   s[2*kt][3],   pah[1], pal[1]);
            pksplit(s[2*kt+1][0], s[2*kt+1][1], pah[2], pal[2]);
            pksplit(s[2*kt+1][2], s[2*kt+1][3], pah[3], pal[3]);
            #pragma unroll
            for (int p2=0; p2<4; p2++){
                unsigned rv[4], rl[4];
                uint32_t off = (uint32_t)((p2*16 + rowB)*ALD + kt*16 + kB)*2;
                ldsm4(rv, vhB + off);
                ldsm4(rl, vlB + off);
                unsigned v0h[2] = {rv[0], rv[1]}, v1h[2] = {rv[2], rv[3]};
                unsigned v0l[2] = {rl[0], rl[1]}, v1l[2] = {rl[2], rl[3]};
                mma_bf16(o[2*p2],   pah, v0h);
                mma_bf16(o[2*p2],   pah, v0l);
                mma_bf16(o[2*p2],   pal, v0h);
                mma_bf16(o[2*p2+1], pah, v1h);
                mma_bf16(o[2*p2+1], pah, v1l);
                mma_bf16(o[2*p2+1], pal, v1h);
            }
        }
        __syncthreads();
    }

    float inva = 1.0f / lsum[0], invb = 1.0f / lsum[1];
    int ra = l0 + warp*16 + g, rb = ra + 8;
    #pragma unroll
    for (int nt=0; nt<8; nt++){
        int c = h*64 + nt*8 + 2*tig;
        unsigned hi, lo;
        size_t basea = ((size_t)(b*Lv + ra))*Dv + c;
        pksplit(o[nt][0]*inva, o[nt][1]*inva, hi, lo);
        *(unsigned*)(g_Oh + basea) = hi;
        *(unsigned*)(g_Ol + basea) = lo;
        size_t baseb = ((size_t)(b*Lv + rb))*Dv + c;
        pksplit(o[nt][2]*invb, o[nt][3]*invb, hi, lo);
        *(unsigned*)(g_Oh + baseb) = hi;
        *(unsigned*)(g_Ol + baseb) = lo;
    }
}

// ---------------- launch ----------------
extern "C" void kernel_launch(void* const* d_in, const int* in_sizes, int n_in,
                              void* d_out, int out_size)
{
    const float* x     = (const float*)d_in[0];
    const float* ctx   = (const float*)d_in[1];
    const int*   cmsk  = (const int*)d_in[2];
    const float* Wq    = (const float*)d_in[3];
    const float* bq    = (const float*)d_in[4];
    const float* Wkv   = (const float*)d_in[5];
    const float* bkv   = (const float*)d_in[6];
    const float* Wproj = (const float*)d_in[7];
    const float* bproj = (const float*)d_in[8];
    float* out         = (float*)d_out;

    bf16 *xh,*xl,*ch,*cl,*wqh,*wql,*wkh,*wkl,*wph,*wpl,*oh,*ol;
    cudaGetSymbolAddress((void**)&xh, g_xh);   cudaGetSymbolAddress((void**)&xl, g_xl);
    cudaGetSymbolAddress((void**)&ch, g_ch);   cudaGetSymbolAddress((void**)&cl, g_cl);
    cudaGetSymbolAddress((void**)&wqh, g_Wqh); cudaGetSymbolAddress((void**)&wql, g_Wql);
    cudaGetSymbolAddress((void**)&wkh, g_Wkh); cudaGetSymbolAddress((void**)&wkl, g_Wkl);
    cudaGetSymbolAddress((void**)&wph, g_Wph); cudaGetSymbolAddress((void**)&wpl, g_Wpl);
    cudaGetSymbolAddress((void**)&oh, g_Oh);   cudaGetSymbolAddress((void**)&ol, g_Ol);

    cudaFuncSetAttribute(hgemm, cudaFuncAttributeMaxDynamicSharedMemorySize, G_SMEM);
    cudaFuncSetAttribute(hattn, cudaFuncAttributeMaxDynamicSharedMemorySize, ATT_SMEM);

    const int NM = Bv*Lv;  // 4096

    mscan<<<Bv, 256>>>(cmsk);                                           // 0
    csplit<<<Bv*Tv, 256>>>(ctx);                                        // 1
    wprep<<<dim3(2*Dv/32, Dv/32), dim3(32,8)>>>(Wkv, wkh, wkl, 2*Dv);   // 2
    hgemm<<<dim3(2*Dv/128, NM/128), 256, G_SMEM>>>(ch, cl, wkh, wkl, bkv, 2, nullptr);     // 3 (ncu slot)
    fsplit<<<NM*Dv/256, 256>>>(x, xh, xl, NM*Dv);                       // 4
    wprep<<<dim3(Dv/32, Dv/32), dim3(32,8)>>>(Wq, wqh, wql, Dv);        // 5
    hgemm<<<dim3(Dv/128, NM/128), 256, G_SMEM>>>(xh, xl, wqh, wql, bq, 1, nullptr);        // 6
    wprep<<<dim3(Dv/32, Dv/32), dim3(32,8)>>>(Wproj, wph, wpl, Dv);     // 7
    vtrans<<<dim3(Tv/32, HDv/32, BHv), dim3(32,8)>>>();                 // 8
    hattn<<<dim3(Lv/64, BHv), 128, ATT_SMEM>>>();                       // 9
    hgemm<<<dim3(Dv/128, NM/128), 256, G_SMEM>>>(oh, ol, wph, wpl, bproj, 0, out);         // 10
}

// round 11
// speedup vs baseline: 1.7135x; 1.3574x over previous
#include <cuda_runtime.h>
#include <cuda_fp16.h>
#include <math.h>
#include <stdint.h>

#define Bv 2
#define Lv 2048
#define Tv 2048
#define Dv 1024
#define Hv 16
#define HDv 64
#define BHv (Bv*Hv)
typedef __half hf;

// ---------------- scratch (zero-initialized device globals) ----------------
__device__ hf g_xh[Bv*Lv*Dv];                    // x single fp16 plane
__device__ hf g_ch[Bv*Tv*Dv];                    // compacted ctx rows, single plane
__device__ hf g_Wqh[Dv*Dv],   g_Wql[Dv*Dv];      // [N][K] fp16 split
__device__ hf g_Wkh[2*Dv*Dv], g_Wkl[2*Dv*Dv];
__device__ hf g_Wph[Dv*Dv],   g_Wpl[Dv*Dv];
__device__ hf g_Qh[BHv*Lv*HDv];                  // [bh][l][hd] single plane (scaled 0.125)
__device__ hf g_Kch[BHv*Tv*HDv], g_Kcl[BHv*Tv*HDv]; // compacted K split
__device__ hf g_Vh[BHv*Tv*HDv], g_Vl[BHv*Tv*HDv];   // compacted V split
__device__ hf g_Vth[BHv*HDv*Tv], g_Vtl[BHv*HDv*Tv]; // compacted V^T split
__device__ hf g_Oh[Bv*Lv*Dv];                    // attention out, single plane
__device__ int g_vidx[Bv][Tv];
__device__ int g_nv[Bv];

// ---------------- helpers ----------------
__device__ __forceinline__ uint32_t smem_u32(const void* p){
    uint32_t a; asm("{ .reg .u64 t; cvta.to.shared.u64 t, %1; cvt.u32.u64 %0, t; }":"=r"(a):"l"(p)); return a;
}
__device__ __forceinline__ void cp16(uint32_t dst, const void* src){
    asm volatile("cp.async.cg.shared.global [%0], [%1], 16;" :: "r"(dst), "l"(src));
}
#define CP_COMMIT() asm volatile("cp.async.commit_group;")
#define CP_WAIT1()  asm volatile("cp.async.wait_group 1;")
#define CP_WAIT0()  asm volatile("cp.async.wait_group 0;")

__device__ __forceinline__ void ldsm4(unsigned r[4], uint32_t a){
    asm volatile("ldmatrix.sync.aligned.m8n8.x4.shared.b16 {%0,%1,%2,%3}, [%4];"
        : "=r"(r[0]), "=r"(r[1]), "=r"(r[2]), "=r"(r[3]) : "r"(a));
}
__device__ __forceinline__ unsigned short h16(float x){ return __half_as_ushort(__float2half_rn(x)); }
__device__ __forceinline__ void hsplit(float x, unsigned short &h, unsigned short &l){
    hf hh = __float2half_rn(x);
    h = __half_as_ushort(hh);
    l = h16(x - __half2float(hh));
}
__device__ __forceinline__ unsigned pkh(float a, float b){
    return (unsigned)h16(a) | ((unsigned)h16(b) << 16);
}
__device__ __forceinline__ void pksplit(float a, float b, unsigned &hi, unsigned &lo){
    unsigned short h0,l0,h1,l1; hsplit(a,h0,l0); hsplit(b,h1,l1);
    hi = (unsigned)h0 | ((unsigned)h1<<16); lo = (unsigned)l0 | ((unsigned)l1<<16);
}
__device__ __forceinline__ void mma_f16(float c[4], const unsigned a[4], const unsigned b[2]){
    asm volatile("mma.sync.aligned.m16n8k16.row.col.f32.f16.f16.f32 "
        "{%0,%1,%2,%3}, {%4,%5,%6,%7}, {%8,%9}, {%0,%1,%2,%3};"
        : "+f"(c[0]), "+f"(c[1]), "+f"(c[2]), "+f"(c[3])
        : "r"(a[0]), "r"(a[1]), "r"(a[2]), "r"(a[3]), "r"(b[0]), "r"(b[1]));
}

// ---------------- prep kernels ----------------
__global__ void fh(const float* __restrict__ in, hf* __restrict__ h, int n){
    int i = blockIdx.x*256 + threadIdx.x;
    if (i < n) h[i] = __float2half_rn(in[i]);
}
// gather valid ctx rows (compacted), single fp16 plane
__global__ void csplit(const float* __restrict__ ctx){
    int row = blockIdx.x;
    int b = row >> 11, j = row & 2047;
    if (j >= g_nv[b]) return;
    const float* p = ctx + ((size_t)b*Tv + g_vidx[b][j])*Dv;
    size_t dst = ((size_t)b*Tv + j)*Dv;
    for (int c = threadIdx.x; c < Dv; c += 256)
        g_ch[dst + c] = __float2half_rn(p[c]);
}
__global__ void wprep(const float* __restrict__ W, hf* __restrict__ th, hf* __restrict__ tl, int N){
    __shared__ float t[32][33];
    int k0 = blockIdx.y*32, n0 = blockIdx.x*32, tx = threadIdx.x, ty = threadIdx.y;
    #pragma unroll
    for (int j=0;j<4;j++) t[ty+j*8][tx] = W[(size_t)(k0+ty+j*8)*N + n0+tx];
    __syncthreads();
    #pragma unroll
    for (int j=0;j<4;j++){
        unsigned short h,l; hsplit(t[tx][ty+j*8], h, l);
        size_t o = (size_t)(n0+ty+j*8)*Dv + k0+tx;
        th[o]=__ushort_as_half(h); tl[o]=__ushort_as_half(l);
    }
}
__global__ void mscan(const int* __restrict__ mask){
    __shared__ int ps[256];
    int b = blockIdx.x, tid = threadIdx.x;
    int v[8]; int cnt = 0;
    #pragma unroll
    for (int i=0;i<8;i++){ v[i] = (mask[b*Tv + tid*8 + i] != 0); cnt += v[i]; }
    ps[tid] = cnt; __syncthreads();
    for (int off=1; off<256; off<<=1){
        int x = (tid >= off) ? ps[tid-off] : 0;
        __syncthreads();
        ps[tid] += x;
        __syncthreads();
    }
    int pre = ps[tid] - cnt;
    #pragma unroll
    for (int i=0;i<8;i++){ if (v[i]) g_vidx[b][pre++] = tid*8 + i; }
    if (tid == 255) g_nv[b] = ps[255];
}
// transpose compacted V planes into [bh][hd][j] (zero tail)
__global__ void vtrans(){
    __shared__ hf t[32][33];
    int bh = blockIdx.z, b = bh>>4;
    int j0 = blockIdx.x*32, hd0 = blockIdx.y*32;
    int tx = threadIdx.x, ty = threadIdx.y;
    int nv = g_nv[b];
    for (int plane=0; plane<2; plane++){
        const hf* src = plane ? g_Vl : g_Vh;
        hf* dst = plane ? g_Vtl : g_Vth;
        #pragma unroll
        for (int jj=0;jj<4;jj++){
            int j = j0 + ty + jj*8;
            hf val = __ushort_as_half((unsigned short)0);
            if (j < nv) val = src[((size_t)bh*Tv + j)*HDv + hd0+tx];
            t[ty+jj*8][tx] = val;
        }
        __syncthreads();
        #pragma unroll
        for (int jj=0;jj<4;jj++)
            dst[((size_t)bh*HDv + hd0+ty+jj*8)*Tv + j0+tx] = t[tx][ty+jj*8];
        __syncthreads();
    }
}

// ---------------- HMMA GEMM: A single fp16 plane, W split 2-plane ----------------
#define GLD 40
#define G_STG (3*128*GLD)
#define G_SMEM (2*G_STG*2)

__global__ __launch_bounds__(256,2) void hgemm(
    const hf* __restrict__ Ag,
    const hf* __restrict__ Wgh, const hf* __restrict__ Wgl,
    const float* __restrict__ bias, int mode, float* __restrict__ outf)
{
    extern __shared__ hf gsm[];
    const uint32_t sbase = smem_u32(gsm);
    const int tid = threadIdx.x, lane = tid&31, warp = tid>>5;
    const int g = lane>>2, tig = lane&3;
    const int wm = warp>>2, wn = warp&3;
    const int m0 = blockIdx.y*128, n0 = blockIdx.x*128;
    if (mode == 2 && (m0 & 2047) >= g_nv[m0 >> 11]) return;
    const int lrow = lane&7, ltile = lane>>3;
    const int rowA = (ltile&1)*8 + lrow, kA = (ltile>>1)*8;
    const int rowB = (ltile>>1)*8 + lrow, kB = (ltile&1)*8;

    float acc[4][4][4] = {};

    auto issue = [&](int buf, int k0){
        #pragma unroll
        for (int t=0;t<6;t++){
            int i = tid + t*256, plane = i>>9, w = i&511, row = w>>2, c4 = (w&3)*8;
            const hf* src = plane==0?Ag : plane==1?Wgh : Wgl;
            int grow = (plane==0?m0:n0) + row;
            cp16(sbase + (uint32_t)(buf*G_STG + plane*(128*GLD) + row*GLD + c4)*2,
                 src + (size_t)grow*1024 + k0 + c4);
        }
        CP_COMMIT();
    };

    issue(0, 0);
    for (int kb=0; kb<32; kb++){
        if (kb < 31) issue((kb+1)&1, (kb+1)*32);
        if (kb < 31) CP_WAIT1(); else CP_WAIT0();
        __syncthreads();
        const uint32_t aB = sbase + (uint32_t)((kb&1)*G_STG)*2;
        const uint32_t bB = aB + 128*GLD*2;
        #pragma unroll
        for (int ks=0; ks<2; ks++){
            unsigned ah[4][4], bh[4][2], bl[4][2];
            #pragma unroll
            for (int mt=0;mt<4;mt++){
                uint32_t off = (uint32_t)((wm*64 + mt*16 + rowA)*GLD + ks*16 + kA)*2;
                ldsm4(ah[mt], aB + off);
            }
            #pragma unroll
            for (int p2=0;p2<2;p2++){
                unsigned r4[4];
                uint32_t off = (uint32_t)((wn*32 + p2*16 + rowB)*GLD + ks*16 + kB)*2;
                ldsm4(r4, bB + off);
                bh[2*p2][0]=r4[0]; bh[2*p2][1]=r4[1]; bh[2*p2+1][0]=r4[2]; bh[2*p2+1][1]=r4[3];
                ldsm4(r4, bB + 128*GLD*2 + off);
                bl[2*p2][0]=r4[0]; bl[2*p2][1]=r4[1]; bl[2*p2+1][0]=r4[2]; bl[2*p2+1][1]=r4[3];
            }
            #pragma unroll
            for (int mt=0;mt<4;mt++)
                #pragma unroll
                for (int nt=0;nt<4;nt++){
                    mma_f16(acc[mt][nt], ah[mt], bh[nt]);
                    mma_f16(acc[mt][nt], ah[mt], bl[nt]);
                }
        }
        __syncthreads();
    }

    #pragma unroll
    for (int mt=0;mt<4;mt++){
        #pragma unroll
        for (int nt=0;nt<4;nt++){
            int r = m0 + wm*64 + mt*16 + g;
            int c = n0 + wn*32 + nt*8 + 2*tig;
            float v00 = acc[mt][nt][0] + bias[c];
            float v01 = acc[mt][nt][1] + bias[c+1];
            float v10 = acc[mt][nt][2] + bias[c];
            float v11 = acc[mt][nt][3] + bias[c+1];
            if (mode == 0){
                *(float2*)(outf + (size_t)r*1024 + c)      = make_float2(v00, v01);
                *(float2*)(outf + (size_t)(r+8)*1024 + c)  = make_float2(v10, v11);
            } else {
                int n2 = c, half = 0;
                if (mode == 2 && c >= 1024){ n2 = c - 1024; half = 1; }
                int h = n2>>6, hd = n2&63;
                #pragma unroll
                for (int rr=0; rr<2; rr++){
                    int m = r + rr*8;
                    int b = m>>11, l = m&2047;
                    float a0 = rr?v10:v00, a1 = rr?v11:v01;
                    size_t base = ((size_t)(b*16 + h)*2048 + l)*64 + hd;
                    if (mode == 1){
                        *(unsigned*)(g_Qh + base) = pkh(a0*0.125f, a1*0.125f);
                    } else if (!half){
                        unsigned hi, lo; pksplit(a0, a1, hi, lo);
                        *(unsigned*)(g_Kch + base) = hi;
                        *(unsigned*)(g_Kcl + base) = lo;
                    } else {
                        unsigned hi, lo; pksplit(a0, a1, hi, lo);
                        *(unsigned*)(g_Vh + base) = hi;
                        *(unsigned*)(g_Vl + base) = lo;
                    }
                }
            }
        }
    }
}

// ---------------- HMMA flash attention (fp16, Q/P single, K/V split) ----------------
#define ALD 72
#define QH_O 0
#define STG0 (64*ALD)
#define A_STG (4*64*ALD)
#define SM_ELEMS (STG0 + 2*A_STG)
#define ATT_SMEM (SM_ELEMS*2)

__global__ __launch_bounds__(128) void hattn()
{
    extern __shared__ hf sm[];
    const uint32_t sbase = smem_u32(sm);
    const int tid = threadIdx.x, lane = tid&31, warp = tid>>5;
    const int g = lane>>2, tig = lane&3;
    const int bh = blockIdx.y, b = bh>>4, h = bh&15, l0 = blockIdx.x*64;
    const int lrow = lane&7, ltile = lane>>3;
    const int rowA = (ltile&1)*8 + lrow, kA = (ltile>>1)*8;
    const int rowB = (ltile>>1)*8 + lrow, kB = (ltile&1)*8;
    const int nv = g_nv[b];
    const int nch = (nv + 63) >> 6;

    auto issueKV = [&](int buf, int t0){
        #pragma unroll
        for (int t=0;t<16;t++){
            int i = tid + t*128, plane = i>>9, w = i&511, row = w>>3, c8 = (w&7)*8;
            const hf* gp;
            if (plane == 0)      gp = g_Kch + ((size_t)bh*Tv + t0 + row)*64 + c8;
            else if (plane == 1) gp = g_Kcl + ((size_t)bh*Tv + t0 + row)*64 + c8;
            else if (plane == 2) gp = g_Vth + ((size_t)bh*HDv + row)*Tv + t0 + c8;
            else                 gp = g_Vtl + ((size_t)bh*HDv + row)*Tv + t0 + c8;
            cp16(sbase + (uint32_t)(STG0 + buf*A_STG + plane*(64*ALD) + row*ALD + c8)*2, gp);
        }
        CP_COMMIT();
    };

    // Q single plane [64][64] -> smem
    #pragma unroll
    for (int t=0;t<4;t++){
        int i = tid + t*128, row = i>>3, c8 = (i&7)*8;
        uint4 v = *(const uint4*)(g_Qh + ((size_t)bh*Lv + l0 + row)*64 + c8);
        *(uint4*)(sm + QH_O + row*ALD + c8) = v;
    }
    issueKV(0, 0);
    __syncthreads();

    unsigned qa[4][4];
    #pragma unroll
    for (int kk=0; kk<4; kk++)
        ldsm4(qa[kk], sbase + (uint32_t)(QH_O + (warp*16 + rowA)*ALD + kk*16 + kA)*2);

    float mold[2] = {-INFINITY, -INFINITY};
    float lsum[2] = {0.f, 0.f};
    float o[8][4] = {};

    for (int ci=0; ci<nch; ci++){
        const int t0 = ci*64;
        if (ci < nch-1) issueKV((ci+1)&1, t0+64);
        if (ci < nch-1) CP_WAIT1(); else CP_WAIT0();
        __syncthreads();

        const uint32_t khB = sbase + (uint32_t)(STG0 + (ci&1)*A_STG)*2;
        const uint32_t klB = khB + 64*ALD*2;
        const uint32_t vhB = khB + 2*64*ALD*2;
        const uint32_t vlB = khB + 3*64*ALD*2;
        const int rem = nv - t0;

        // S = Q (Kh + Kl)^T
        float s[8][4] = {};
        #pragma unroll
        for (int kk=0; kk<4; kk++){
            unsigned bhf[8][2], blf[8][2];
            #pragma unroll
            for (int p2=0; p2<4; p2++){
                unsigned r4[4];
                uint32_t off = (uint32_t)((p2*16 + rowB)*ALD + kk*16 + kB)*2;
                ldsm4(r4, khB + off);
                bhf[2*p2][0]=r4[0]; bhf[2*p2][1]=r4[1]; bhf[2*p2+1][0]=r4[2]; bhf[2*p2+1][1]=r4[3];
                ldsm4(r4, klB + off);
                blf[2*p2][0]=r4[0]; blf[2*p2][1]=r4[1]; blf[2*p2+1][0]=r4[2]; blf[2*p2+1][1]=r4[3];
            }
            #pragma unroll
            for (int nt=0; nt<8; nt++){
                mma_f16(s[nt], qa[kk], bhf[nt]);
                mma_f16(s[nt], qa[kk], blf[nt]);
            }
        }

        float ma = mold[0], mb = mold[1];
        #pragma unroll
        for (int nt=0; nt<8; nt++){
            int c = nt*8 + 2*tig;
            if (c   >= rem){ s[nt][0] = -1e9f; s[nt][2] = -1e9f; }
            if (c+1 >= rem){ s[nt][1] = -1e9f; s[nt][3] = -1e9f; }
            ma = fmaxf(ma, fmaxf(s[nt][0], s[nt][1]));
            mb = fmaxf(mb, fmaxf(s[nt][2], s[nt][3]));
        }
        ma = fmaxf(ma, __shfl_xor_sync(0xffffffffu, ma, 1));
        ma = fmaxf(ma, __shfl_xor_sync(0xffffffffu, ma, 2));
        mb = fmaxf(mb, __shfl_xor_sync(0xffffffffu, mb, 1));
        mb = fmaxf(mb, __shfl_xor_sync(0xffffffffu, mb, 2));

        float aa = __expf(mold[0] - ma), ab = __expf(mold[1] - mb);
        float suma = 0.f, sumb = 0.f;
        #pragma unroll
        for (int nt=0; nt<8; nt++){
            s[nt][0] = __expf(s[nt][0] - ma);
            s[nt][1] = __expf(s[nt][1] - ma);
            s[nt][2] = __expf(s[nt][2] - mb);
            s[nt][3] = __expf(s[nt][3] - mb);
            suma += s[nt][0] + s[nt][1];
            sumb += s[nt][2] + s[nt][3];
        }
        suma += __shfl_xor_sync(0xffffffffu, suma, 1);
        suma += __shfl_xor_sync(0xffffffffu, suma, 2);
        sumb += __shfl_xor_sync(0xffffffffu, sumb, 1);
        sumb += __shfl_xor_sync(0xffffffffu, sumb, 2);
        lsum[0] = lsum[0]*aa + suma;  mold[0] = ma;
        lsum[1] = lsum[1]*ab + sumb;  mold[1] = mb;
        #pragma unroll
        for (int nt=0; nt<8; nt++){
            o[nt][0] *= aa; o[nt][1] *= aa; o[nt][2] *= ab; o[nt][3] *= ab;
        }

        // PV: P single fp16, V = Vh + Vl
        #pragma unroll
        for (int kt=0; kt<4; kt++){
            unsigned pa[4];
            pa[0] = pkh(s[2*kt][0],   s[2*kt][1]);
            pa[1] = pkh(s[2*kt][2],   s[2*kt][3]);
            pa[2] = pkh(s[2*kt+1][0], s[2*kt+1][1]);
            pa[3] = pkh(s[2*kt+1][2], s[2*kt+1][3]);
            #pragma unroll
            for (int p2=0; p2<4; p2++){
                unsigned rv[4], rl[4];
                uint32_t off = (uint32_t)((p2*16 + rowB)*ALD + kt*16 + kB)*2;
                ldsm4(rv, vhB + off);
                ldsm4(rl, vlB + off);
                unsigned v0h[2] = {rv[0], rv[1]}, v1h[2] = {rv[2], rv[3]};
                unsigned v0l[2] = {rl[0], rl[1]}, v1l[2] = {rl[2], rl[3]};
                mma_f16(o[2*p2],   pa, v0h);
                mma_f16(o[2*p2],   pa, v0l);
                mma_f16(o[2*p2+1], pa, v1h);
                mma_f16(o[2*p2+1], pa, v1l);
            }
        }
        __syncthreads();
    }

    float inva = 1.0f / lsum[0], invb = 1.0f / lsum[1];
    int ra = l0 + warp*16 + g, rb = ra + 8;
    #pragma unroll
    for (int nt=0; nt<8; nt++){
        int c = h*64 + nt*8 + 2*tig;
        *(unsigned*)(g_Oh + ((size_t)(b*Lv + ra))*Dv + c) = pkh(o[nt][0]*inva, o[nt][1]*inva);
        *(unsigned*)(g_Oh + ((size_t)(b*Lv + rb))*Dv + c) = pkh(o[nt][2]*invb, o[nt][3]*invb);
    }
}

// ---------------- launch ----------------
extern "C" void kernel_launch(void* const* d_in, const int* in_sizes, int n_in,
                              void* d_out, int out_size)
{
    const float* x     = (const float*)d_in[0];
    const float* ctx   = (const float*)d_in[1];
    const int*   cmsk  = (const int*)d_in[2];
    const float* Wq    = (const float*)d_in[3];
    const float* bq    = (const float*)d_in[4];
    const float* Wkv   = (const float*)d_in[5];
    const float* bkv   = (const float*)d_in[6];
    const float* Wproj = (const float*)d_in[7];
    const float* bproj = (const float*)d_in[8];
    float* out         = (float*)d_out;

    hf *xh,*ch,*wqh,*wql,*wkh,*wkl,*wph,*wpl,*oh;
    cudaGetSymbolAddress((void**)&xh, g_xh);
    cudaGetSymbolAddress((void**)&ch, g_ch);
    cudaGetSymbolAddress((void**)&wqh, g_Wqh); cudaGetSymbolAddress((void**)&wql, g_Wql);
    cudaGetSymbolAddress((void**)&wkh, g_Wkh); cudaGetSymbolAddress((void**)&wkl, g_Wkl);
    cudaGetSymbolAddress((void**)&wph, g_Wph); cudaGetSymbolAddress((void**)&wpl, g_Wpl);
    cudaGetSymbolAddress((void**)&oh, g_Oh);

    cudaFuncSetAttribute(hgemm, cudaFuncAttributeMaxDynamicSharedMemorySize, G_SMEM);
    cudaFuncSetAttribute(hattn, cudaFuncAttributeMaxDynamicSharedMemorySize, ATT_SMEM);

    const int NM = Bv*Lv;  // 4096

    mscan<<<Bv, 256>>>(cmsk);                                           // 0
    csplit<<<Bv*Tv, 256>>>(ctx);                                        // 1
    wprep<<<dim3(2*Dv/32, Dv/32), dim3(32,8)>>>(Wkv, wkh, wkl, 2*Dv);   // 2
    hgemm<<<dim3(2*Dv/128, NM/128), 256, G_SMEM>>>(ch, wkh, wkl, bkv, 2, nullptr);   // 3 (ncu slot)
    fh<<<NM*Dv/256, 256>>>(x, xh, NM*Dv);                               // 4
    wprep<<<dim3(Dv/32, Dv/32), dim3(32,8)>>>(Wq, wqh, wql, Dv);        // 5
    hgemm<<<dim3(Dv/128, NM/128), 256, G_SMEM>>>(xh, wqh, wql, bq, 1, nullptr);      // 6
    wprep<<<dim3(Dv/32, Dv/32), dim3(32,8)>>>(Wproj, wph, wpl, Dv);     // 7
    vtrans<<<dim3(Tv/32, HDv/32, BHv), dim3(32,8)>>>();                 // 8
    hattn<<<dim3(Lv/64, BHv), 128, ATT_SMEM>>>();                       // 9
    hgemm<<<dim3(Dv/128, NM/128), 256, G_SMEM>>>(oh, wph, wpl, bproj, 0, out);       // 10
}

// round 12
// speedup vs baseline: 2.0952x; 1.2228x over previous
#include <cuda_runtime.h>
#include <cuda_fp16.h>
#include <math.h>
#include <stdint.h>

#define Bv 2
#define Lv 2048
#define Tv 2048
#define Dv 1024
#define Hv 16
#define HDv 64
#define BHv (Bv*Hv)
typedef __half hf;

// ---------------- scratch ----------------
__device__ hf g_xh[Bv*Lv*Dv];                    // x single fp16 plane
__device__ hf g_ch[Bv*Tv*Dv];                    // compacted ctx rows, single plane
__device__ hf g_Wqh[Dv*Dv],   g_Wql[Dv*Dv];      // [N][K] fp16 split
__device__ hf g_Wkh[2*Dv*Dv], g_Wkl[2*Dv*Dv];
__device__ hf g_Wph[Dv*Dv],   g_Wpl[Dv*Dv];
__device__ hf g_Qh[BHv*Lv*HDv];                  // [bh][l][hd] single plane (scaled 0.125)
__device__ hf g_Kch[BHv*Tv*HDv];                 // compacted K single plane
__device__ hf g_Vh[BHv*Tv*HDv];                  // compacted V single plane
__device__ hf g_Vth[BHv*HDv*Tv];                 // compacted V^T single plane
__device__ hf g_Oh[Bv*Lv*Dv];                    // attention out, single plane
__device__ int g_vidx[Bv][Tv];
__device__ int g_nv[Bv];

// ---------------- helpers ----------------
__device__ __forceinline__ uint32_t smem_u32(const void* p){
    uint32_t a; asm("{ .reg .u64 t; cvta.to.shared.u64 t, %1; cvt.u32.u64 %0, t; }":"=r"(a):"l"(p)); return a;
}
__device__ __forceinline__ void cp16(uint32_t dst, const void* src){
    asm volatile("cp.async.cg.shared.global [%0], [%1], 16;" :: "r"(dst), "l"(src));
}
#define CP_COMMIT() asm volatile("cp.async.commit_group;")
#define CP_WAIT1()  asm volatile("cp.async.wait_group 1;")
#define CP_WAIT0()  asm volatile("cp.async.wait_group 0;")

__device__ __forceinline__ void ldsm4(unsigned r[4], uint32_t a){
    asm volatile("ldmatrix.sync.aligned.m8n8.x4.shared.b16 {%0,%1,%2,%3}, [%4];"
        : "=r"(r[0]), "=r"(r[1]), "=r"(r[2]), "=r"(r[3]) : "r"(a));
}
__device__ __forceinline__ unsigned short h16(float x){ return __half_as_ushort(__float2half_rn(x)); }
__device__ __forceinline__ void hsplit(float x, unsigned short &h, unsigned short &l){
    hf hh = __float2half_rn(x);
    h = __half_as_ushort(hh);
    l = h16(x - __half2float(hh));
}
__device__ __forceinline__ unsigned pkh(float a, float b){
    return (unsigned)h16(a) | ((unsigned)h16(b) << 16);
}
__device__ __forceinline__ void pksplit(float a, float b, unsigned &hi, unsigned &lo){
    unsigned short h0,l0,h1,l1; hsplit(a,h0,l0); hsplit(b,h1,l1);
    hi = (unsigned)h0 | ((unsigned)h1<<16); lo = (unsigned)l0 | ((unsigned)l1<<16);
}
__device__ __forceinline__ void mma_f16(float c[4], const unsigned a[4], const unsigned b[2]){
    asm volatile("mma.sync.aligned.m16n8k16.row.col.f32.f16.f16.f32 "
        "{%0,%1,%2,%3}, {%4,%5,%6,%7}, {%8,%9}, {%0,%1,%2,%3};"
        : "+f"(c[0]), "+f"(c[1]), "+f"(c[2]), "+f"(c[3])
        : "r"(a[0]), "r"(a[1]), "r"(a[2]), "r"(a[3]), "r"(b[0]), "r"(b[1]));
}

// ---------------- prep kernels ----------------
__global__ void fh(const float* __restrict__ in, hf* __restrict__ h, int n){
    int i = blockIdx.x*256 + threadIdx.x;
    if (i < n) h[i] = __float2half_rn(in[i]);
}
__global__ void csplit(const float* __restrict__ ctx){
    int row = blockIdx.x;
    int b = row >> 11, j = row & 2047;
    if (j >= g_nv[b]) return;
    const float* p = ctx + ((size_t)b*Tv + g_vidx[b][j])*Dv;
    size_t dst = ((size_t)b*Tv + j)*Dv;
    for (int c = threadIdx.x; c < Dv; c += 256)
        g_ch[dst + c] = __float2half_rn(p[c]);
}
__global__ void wprep(const float* __restrict__ W, hf* __restrict__ th, hf* __restrict__ tl, int N){
    __shared__ float t[32][33];
    int k0 = blockIdx.y*32, n0 = blockIdx.x*32, tx = threadIdx.x, ty = threadIdx.y;
    #pragma unroll
    for (int j=0;j<4;j++) t[ty+j*8][tx] = W[(size_t)(k0+ty+j*8)*N + n0+tx];
    __syncthreads();
    #pragma unroll
    for (int j=0;j<4;j++){
        unsigned short h,l; hsplit(t[tx][ty+j*8], h, l);
        size_t o = (size_t)(n0+ty+j*8)*Dv + k0+tx;
        th[o]=__ushort_as_half(h); tl[o]=__ushort_as_half(l);
    }
}
__global__ void mscan(const int* __restrict__ mask){
    __shared__ int ps[256];
    int b = blockIdx.x, tid = threadIdx.x;
    int v[8]; int cnt = 0;
    #pragma unroll
    for (int i=0;i<8;i++){ v[i] = (mask[b*Tv + tid*8 + i] != 0); cnt += v[i]; }
    ps[tid] = cnt; __syncthreads();
    for (int off=1; off<256; off<<=1){
        int x = (tid >= off) ? ps[tid-off] : 0;
        __syncthreads();
        ps[tid] += x;
        __syncthreads();
    }
    int pre = ps[tid] - cnt;
    #pragma unroll
    for (int i=0;i<8;i++){ if (v[i]) g_vidx[b][pre++] = tid*8 + i; }
    if (tid == 255) g_nv[b] = ps[255];
}
// transpose compacted V into [bh][hd][j] (zero tail)
__global__ void vtrans(){
    __shared__ hf t[32][33];
    int bh = blockIdx.z, b = bh>>4;
    int j0 = blockIdx.x*32, hd0 = blockIdx.y*32;
    int tx = threadIdx.x, ty = threadIdx.y;
    int nv = g_nv[b];
    #pragma unroll
    for (int jj=0;jj<4;jj++){
        int j = j0 + ty + jj*8;
        hf val = __ushort_as_half((unsigned short)0);
        if (j < nv) val = g_Vh[((size_t)bh*Tv + j)*HDv + hd0+tx];
        t[ty+jj*8][tx] = val;
    }
    __syncthreads();
    #pragma unroll
    for (int jj=0;jj<4;jj++)
        g_Vth[((size_t)bh*HDv + hd0+ty+jj*8)*Tv + j0+tx] = t[tx][ty+jj*8];
}

// ---------------- HMMA GEMM: A single fp16 plane, W split 2-plane ----------------
#define GLD 40
#define G_STG (3*128*GLD)
#define G_SMEM (2*G_STG*2)

__global__ __launch_bounds__(256,2) void hgemm(
    const hf* __restrict__ Ag,
    const hf* __restrict__ Wgh, const hf* __restrict__ Wgl,
    const float* __restrict__ bias, int mode, float* __restrict__ outf)
{
    extern __shared__ hf gsm[];
    const uint32_t sbase = smem_u32(gsm);
    const int tid = threadIdx.x, lane = tid&31, warp = tid>>5;
    const int g = lane>>2, tig = lane&3;
    const int wm = warp>>2, wn = warp&3;
    const int m0 = blockIdx.y*128, n0 = blockIdx.x*128;
    if (mode == 2 && (m0 & 2047) >= g_nv[m0 >> 11]) return;
    const int lrow = lane&7, ltile = lane>>3;
    const int rowA = (ltile&1)*8 + lrow, kA = (ltile>>1)*8;
    const int rowB = (ltile>>1)*8 + lrow, kB = (ltile&1)*8;

    float acc[4][4][4] = {};

    auto issue = [&](int buf, int k0){
        #pragma unroll
        for (int t=0;t<6;t++){
            int i = tid + t*256, plane = i>>9, w = i&511, row = w>>2, c4 = (w&3)*8;
            const hf* src = plane==0?Ag : plane==1?Wgh : Wgl;
            int grow = (plane==0?m0:n0) + row;
            cp16(sbase + (uint32_t)(buf*G_STG + plane*(128*GLD) + row*GLD + c4)*2,
                 src + (size_t)grow*1024 + k0 + c4);
        }
        CP_COMMIT();
    };

    issue(0, 0);
    for (int kb=0; kb<32; kb++){
        if (kb < 31) issue((kb+1)&1, (kb+1)*32);
        if (kb < 31) CP_WAIT1(); else CP_WAIT0();
        __syncthreads();
        const uint32_t aB = sbase + (uint32_t)((kb&1)*G_STG)*2;
        const uint32_t bB = aB + 128*GLD*2;
        #pragma unroll
        for (int ks=0; ks<2; ks++){
            unsigned ah[4][4], bh[4][2], bl[4][2];
            #pragma unroll
            for (int mt=0;mt<4;mt++){
                uint32_t off = (uint32_t)((wm*64 + mt*16 + rowA)*GLD + ks*16 + kA)*2;
                ldsm4(ah[mt], aB + off);
            }
            #pragma unroll
            for (int p2=0;p2<2;p2++){
                unsigned r4[4];
                uint32_t off = (uint32_t)((wn*32 + p2*16 + rowB)*GLD + ks*16 + kB)*2;
                ldsm4(r4, bB + off);
                bh[2*p2][0]=r4[0]; bh[2*p2][1]=r4[1]; bh[2*p2+1][0]=r4[2]; bh[2*p2+1][1]=r4[3];
                ldsm4(r4, bB + 128*GLD*2 + off);
                bl[2*p2][0]=r4[0]; bl[2*p2][1]=r4[1]; bl[2*p2+1][0]=r4[2]; bl[2*p2+1][1]=r4[3];
            }
            #pragma unroll
            for (int mt=0;mt<4;mt++)
                #pragma unroll
                for (int nt=0;nt<4;nt++){
                    mma_f16(acc[mt][nt], ah[mt], bh[nt]);
                    mma_f16(acc[mt][nt], ah[mt], bl[nt]);
                }
        }
        __syncthreads();
    }

    #pragma unroll
    for (int mt=0;mt<4;mt++){
        #pragma unroll
        for (int nt=0;nt<4;nt++){
            int r = m0 + wm*64 + mt*16 + g;
            int c = n0 + wn*32 + nt*8 + 2*tig;
            float v00 = acc[mt][nt][0] + bias[c];
            float v01 = acc[mt][nt][1] + bias[c+1];
            float v10 = acc[mt][nt][2] + bias[c];
            float v11 = acc[mt][nt][3] + bias[c+1];
            if (mode == 0){
                *(float2*)(outf + (size_t)r*1024 + c)      = make_float2(v00, v01);
                *(float2*)(outf + (size_t)(r+8)*1024 + c)  = make_float2(v10, v11);
            } else {
                int n2 = c, half = 0;
                if (mode == 2 && c >= 1024){ n2 = c - 1024; half = 1; }
                int h = n2>>6, hd = n2&63;
                #pragma unroll
                for (int rr=0; rr<2; rr++){
                    int m = r + rr*8;
                    int b = m>>11, l = m&2047;
                    float a0 = rr?v10:v00, a1 = rr?v11:v01;
                    size_t base = ((size_t)(b*16 + h)*2048 + l)*64 + hd;
                    if (mode == 1)      *(unsigned*)(g_Qh  + base) = pkh(a0*0.125f, a1*0.125f);
                    else if (!half)     *(unsigned*)(g_Kch + base) = pkh(a0, a1);
                    else                *(unsigned*)(g_Vh  + base) = pkh(a0, a1);
                }
            }
        }
    }
}

// ---------------- HMMA flash attention (all-fp16 single-pass, 64 q/CTA) ----------------
#define ALD 72
#define QH_O 0
#define STG0 (64*ALD)
#define A_STG (2*64*ALD)            // per-stage: K, Vt single planes
#define SM_ELEMS (STG0 + 2*A_STG)   // 23040 hf = 46 KB
#define ATT_SMEM (SM_ELEMS*2)

__global__ __launch_bounds__(128) void hattn()
{
    extern __shared__ hf sm[];
    const uint32_t sbase = smem_u32(sm);
    const int tid = threadIdx.x, lane = tid&31, warp = tid>>5;
    const int g = lane>>2, tig = lane&3;
    const int bh = blockIdx.y, b = bh>>4, h = bh&15, l0 = blockIdx.x*64;
    const int lrow = lane&7, ltile = lane>>3;
    const int rowA = (ltile&1)*8 + lrow, kA = (ltile>>1)*8;
    const int rowB = (ltile>>1)*8 + lrow, kB = (ltile&1)*8;
    const int nv = g_nv[b];
    const int nch = (nv + 63) >> 6;

    auto issueKV = [&](int buf, int t0){
        #pragma unroll
        for (int t=0;t<8;t++){
            int i = tid + t*128, plane = i>>9, w = i&511, row = w>>3, c8 = (w&7)*8;
            const hf* gp;
            if (plane == 0) gp = g_Kch + ((size_t)bh*Tv + t0 + row)*64 + c8;
            else            gp = g_Vth + ((size_t)bh*HDv + row)*Tv + t0 + c8;
            cp16(sbase + (uint32_t)(STG0 + buf*A_STG + plane*(64*ALD) + row*ALD + c8)*2, gp);
        }
        CP_COMMIT();
    };

    // Q single plane [64][64] -> smem
    #pragma unroll
    for (int t=0;t<4;t++){
        int i = tid + t*128, row = i>>3, c8 = (i&7)*8;
        uint4 v = *(const uint4*)(g_Qh + ((size_t)bh*Lv + l0 + row)*64 + c8);
        *(uint4*)(sm + QH_O + row*ALD + c8) = v;
    }
    issueKV(0, 0);
    __syncthreads();

    unsigned qa[4][4];
    #pragma unroll
    for (int kk=0; kk<4; kk++)
        ldsm4(qa[kk], sbase + (uint32_t)(QH_O + (warp*16 + rowA)*ALD + kk*16 + kA)*2);

    float mold[2] = {-INFINITY, -INFINITY};
    float lsum[2] = {0.f, 0.f};
    float o[8][4] = {};

    for (int ci=0; ci<nch; ci++){
        const int t0 = ci*64;
        if (ci < nch-1) issueKV((ci+1)&1, t0+64);
        if (ci < nch-1) CP_WAIT1(); else CP_WAIT0();
        __syncthreads();

        const uint32_t khB = sbase + (uint32_t)(STG0 + (ci&1)*A_STG)*2;
        const uint32_t vhB = khB + 64*ALD*2;
        const int rem = nv - t0;

        // S = Q K^T (single pass)
        float s[8][4] = {};
        #pragma unroll
        for (int kk=0; kk<4; kk++){
            unsigned bhf[8][2];
            #pragma unroll
            for (int p2=0; p2<4; p2++){
                unsigned r4[4];
                uint32_t off = (uint32_t)((p2*16 + rowB)*ALD + kk*16 + kB)*2;
                ldsm4(r4, khB + off);
                bhf[2*p2][0]=r4[0]; bhf[2*p2][1]=r4[1]; bhf[2*p2+1][0]=r4[2]; bhf[2*p2+1][1]=r4[3];
            }
            #pragma unroll
            for (int nt=0; nt<8; nt++)
                mma_f16(s[nt], qa[kk], bhf[nt]);
        }

        float ma = mold[0], mb = mold[1];
        #pragma unroll
        for (int nt=0; nt<8; nt++){
            int c = nt*8 + 2*tig;
            if (c   >= rem){ s[nt][0] = -1e9f; s[nt][2] = -1e9f; }
            if (c+1 >= rem){ s[nt][1] = -1e9f; s[nt][3] = -1e9f; }
            ma = fmaxf(ma, fmaxf(s[nt][0], s[nt][1]));
            mb = fmaxf(mb, fmaxf(s[nt][2], s[nt][3]));
        }
        ma = fmaxf(ma, __shfl_xor_sync(0xffffffffu, ma, 1));
        ma = fmaxf(ma, __shfl_xor_sync(0xffffffffu, ma, 2));
        mb = fmaxf(mb, __shfl_xor_sync(0xffffffffu, mb, 1));
        mb = fmaxf(mb, __shfl_xor_sync(0xffffffffu, mb, 2));

        float aa = __expf(mold[0] - ma), ab = __expf(mold[1] - mb);
        float suma = 0.f, sumb = 0.f;
        #pragma unroll
        for (int nt=0; nt<8; nt++){
            s[nt][0] = __expf(s[nt][0] - ma);
            s[nt][1] = __expf(s[nt][1] - ma);
            s[nt][2] = __expf(s[nt][2] - mb);
            s[nt][3] = __expf(s[nt][3] - mb);
            suma += s[nt][0] + s[nt][1];
            sumb += s[nt][2] + s[nt][3];
        }
        suma += __shfl_xor_sync(0xffffffffu, suma, 1);
        suma += __shfl_xor_sync(0xffffffffu, suma, 2);
        sumb += __shfl_xor_sync(0xffffffffu, sumb, 1);
        sumb += __shfl_xor_sync(0xffffffffu, sumb, 2);
        lsum[0] = lsum[0]*aa + suma;  mold[0] = ma;
        lsum[1] = lsum[1]*ab + sumb;  mold[1] = mb;
        #pragma unroll
        for (int nt=0; nt<8; nt++){
            o[nt][0] *= aa; o[nt][1] *= aa; o[nt][2] *= ab; o[nt][3] *= ab;
        }

        // PV single pass
        #pragma unroll
        for (int kt=0; kt<4; kt++){
            unsigned pa[4];
            pa[0] = pkh(s[2*kt][0],   s[2*kt][1]);
            pa[1] = pkh(s[2*kt][2],   s[2*kt][3]);
            pa[2] = pkh(s[2*kt+1][0], s[2*kt+1][1]);
            pa[3] = pkh(s[2*kt+1][2], s[2*kt+1][3]);
            #pragma unroll
            for (int p2=0; p2<4; p2++){
                unsigned rv[4];
                uint32_t off = (uint32_t)((p2*16 + rowB)*ALD + kt*16 + kB)*2;
                ldsm4(rv, vhB + off);
                unsigned v0[2] = {rv[0], rv[1]}, v1[2] = {rv[2], rv[3]};
                mma_f16(o[2*p2],   pa, v0);
                mma_f16(o[2*p2+1], pa, v1);
            }
        }
        __syncthreads();
    }

    float inva = 1.0f / lsum[0], invb = 1.0f / lsum[1];
    int ra = l0 + warp*16 + g, rb = ra + 8;
    #pragma unroll
    for (int nt=0; nt<8; nt++){
        int c = h*64 + nt*8 + 2*tig;
        *(unsigned*)(g_Oh + ((size_t)(b*Lv + ra))*Dv + c) = pkh(o[nt][0]*inva, o[nt][1]*inva);
        *(unsigned*)(g_Oh + ((size_t)(b*Lv + rb))*Dv + c) = pkh(o[nt][2]*invb, o[nt][3]*invb);
    }
}

// ---------------- launch ----------------
extern "C" void kernel_launch(void* const* d_in, const int* in_sizes, int n_in,
                              void* d_out, int out_size)
{
    const float* x     = (const float*)d_in[0];
    const float* ctx   = (const float*)d_in[1];
    const int*   cmsk  = (const int*)d_in[2];
    const float* Wq    = (const float*)d_in[3];
    const float* bq    = (const float*)d_in[4];
    const float* Wkv   = (const float*)d_in[5];
    const float* bkv   = (const float*)d_in[6];
    const float* Wproj = (const float*)d_in[7];
    const float* bproj = (const float*)d_in[8];
    float* out         = (float*)d_out;

    hf *xh,*ch,*wqh,*wql,*wkh,*wkl,*wph,*wpl,*oh;
    cudaGetSymbolAddress((void**)&xh, g_xh);
    cudaGetSymbolAddress((void**)&ch, g_ch);
    cudaGetSymbolAddress((void**)&wqh, g_Wqh); cudaGetSymbolAddress((void**)&wql, g_Wql);
    cudaGetSymbolAddress((void**)&wkh, g_Wkh); cudaGetSymbolAddress((void**)&wkl, g_Wkl);
    cudaGetSymbolAddress((void**)&wph, g_Wph); cudaGetSymbolAddress((void**)&wpl, g_Wpl);
    cudaGetSymbolAddress((void**)&oh, g_Oh);

    cudaFuncSetAttribute(hgemm, cudaFuncAttributeMaxDynamicSharedMemorySize, G_SMEM);
    cudaFuncSetAttribute(hattn, cudaFuncAttributeMaxDynamicSharedMemorySize, ATT_SMEM);

    const int NM = Bv*Lv;  // 4096

    mscan<<<Bv, 256>>>(cmsk);                                           // 0
    csplit<<<Bv*Tv, 256>>>(ctx);                                        // 1
    wprep<<<dim3(2*Dv/32, Dv/32), dim3(32,8)>>>(Wkv, wkh, wkl, 2*Dv);   // 2
    hgemm<<<dim3(2*Dv/128, NM/128), 256, G_SMEM>>>(ch, wkh, wkl, bkv, 2, nullptr);   // 3 (ncu slot)
    fh<<<NM*Dv/256, 256>>>(x, xh, NM*Dv);                               // 4
    wprep<<<dim3(Dv/32, Dv/32), dim3(32,8)>>>(Wq, wqh, wql, Dv);        // 5
    hgemm<<<dim3(Dv/128, NM/128), 256, G_SMEM>>>(xh, wqh, wql, bq, 1, nullptr);      // 6
    wprep<<<dim3(Dv/32, Dv/32), dim3(32,8)>>>(Wproj, wph, wpl, Dv);     // 7
    vtrans<<<dim3(Tv/32, HDv/32, BHv), dim3(32,8)>>>();                 // 8
    hattn<<<dim3(Lv/64, BHv), 128, ATT_SMEM>>>();                       // 9
    hgemm<<<dim3(Dv/128, NM/128), 256, G_SMEM>>>(oh, wph, wpl, bproj, 0, out);       // 10
}

// round 13
// speedup vs baseline: 2.6552x; 1.2672x over previous
#include <cuda_runtime.h>
#include <cuda_fp16.h>
#include <math.h>
#include <stdint.h>

#define Bv 2
#define Lv 2048
#define Tv 2048
#define Dv 1024
#define Hv 16
#define HDv 64
#define BHv (Bv*Hv)
typedef __half hf;

// ---------------- scratch ----------------
__device__ hf g_xh[Bv*Lv*Dv];                    // x fp16
__device__ hf g_ch[Bv*Tv*Dv];                    // compacted ctx rows
__device__ hf g_Wqh[Dv*Dv];                      // [N][K] fp16
__device__ hf g_Wkh[2*Dv*Dv];
__device__ hf g_Wph[Dv*Dv];
__device__ hf g_Qh[BHv*Lv*HDv];                  // [bh][l][hd] (scaled 0.125)
__device__ hf g_Kch[BHv*Tv*HDv];                 // compacted K
__device__ hf g_Vh[BHv*Tv*HDv];                  // compacted V
__device__ hf g_Vth[BHv*HDv*Tv];                 // compacted V^T
__device__ hf g_Oh[Bv*Lv*Dv];                    // attention out
__device__ int g_vidx[Bv][Tv];
__device__ int g_nv[Bv];

// ---------------- helpers ----------------
__device__ __forceinline__ uint32_t smem_u32(const void* p){
    uint32_t a; asm("{ .reg .u64 t; cvta.to.shared.u64 t, %1; cvt.u32.u64 %0, t; }":"=r"(a):"l"(p)); return a;
}
__device__ __forceinline__ void cp16(uint32_t dst, const void* src){
    asm volatile("cp.async.cg.shared.global [%0], [%1], 16;" :: "r"(dst), "l"(src));
}
#define CP_COMMIT() asm volatile("cp.async.commit_group;")
#define CP_WAIT1()  asm volatile("cp.async.wait_group 1;")
#define CP_WAIT0()  asm volatile("cp.async.wait_group 0;")

__device__ __forceinline__ void ldsm4(unsigned r[4], uint32_t a){
    asm volatile("ldmatrix.sync.aligned.m8n8.x4.shared.b16 {%0,%1,%2,%3}, [%4];"
        : "=r"(r[0]), "=r"(r[1]), "=r"(r[2]), "=r"(r[3]) : "r"(a));
}
__device__ __forceinline__ unsigned short h16(float x){ return __half_as_ushort(__float2half_rn(x)); }
__device__ __forceinline__ unsigned pkh(float a, float b){
    return (unsigned)h16(a) | ((unsigned)h16(b) << 16);
}
__device__ __forceinline__ void mma_f16(float c[4], const unsigned a[4], const unsigned b[2]){
    asm volatile("mma.sync.aligned.m16n8k16.row.col.f32.f16.f16.f32 "
        "{%0,%1,%2,%3}, {%4,%5,%6,%7}, {%8,%9}, {%0,%1,%2,%3};"
        : "+f"(c[0]), "+f"(c[1]), "+f"(c[2]), "+f"(c[3])
        : "r"(a[0]), "r"(a[1]), "r"(a[2]), "r"(a[3]), "r"(b[0]), "r"(b[1]));
}

// ---------------- prep kernels ----------------
__global__ void fh(const float* __restrict__ in, hf* __restrict__ h, int n){
    int i = blockIdx.x*256 + threadIdx.x;
    if (i < n) h[i] = __float2half_rn(in[i]);
}
__global__ void csplit(const float* __restrict__ ctx){
    int row = blockIdx.x;
    int b = row >> 11, j = row & 2047;
    if (j >= g_nv[b]) return;
    const float* p = ctx + ((size_t)b*Tv + g_vidx[b][j])*Dv;
    size_t dst = ((size_t)b*Tv + j)*Dv;
    for (int c = threadIdx.x; c < Dv; c += 256)
        g_ch[dst + c] = __float2half_rn(p[c]);
}
__global__ void wprep(const float* __restrict__ W, hf* __restrict__ th, int N){
    __shared__ float t[32][33];
    int k0 = blockIdx.y*32, n0 = blockIdx.x*32, tx = threadIdx.x, ty = threadIdx.y;
    #pragma unroll
    for (int j=0;j<4;j++) t[ty+j*8][tx] = W[(size_t)(k0+ty+j*8)*N + n0+tx];
    __syncthreads();
    #pragma unroll
    for (int j=0;j<4;j++)
        th[(size_t)(n0+ty+j*8)*Dv + k0+tx] = __float2half_rn(t[tx][ty+j*8]);
}
__global__ void mscan(const int* __restrict__ mask){
    __shared__ int ps[256];
    int b = blockIdx.x, tid = threadIdx.x;
    int v[8]; int cnt = 0;
    #pragma unroll
    for (int i=0;i<8;i++){ v[i] = (mask[b*Tv + tid*8 + i] != 0); cnt += v[i]; }
    ps[tid] = cnt; __syncthreads();
    for (int off=1; off<256; off<<=1){
        int x = (tid >= off) ? ps[tid-off] : 0;
        __syncthreads();
        ps[tid] += x;
        __syncthreads();
    }
    int pre = ps[tid] - cnt;
    #pragma unroll
    for (int i=0;i<8;i++){ if (v[i]) g_vidx[b][pre++] = tid*8 + i; }
    if (tid == 255) g_nv[b] = ps[255];
}
// transpose compacted V into [bh][hd][j] (zero tail)
__global__ void vtrans(){
    __shared__ hf t[32][33];
    int bh = blockIdx.z, b = bh>>4;
    int j0 = blockIdx.x*32, hd0 = blockIdx.y*32;
    int tx = threadIdx.x, ty = threadIdx.y;
    int nv = g_nv[b];
    #pragma unroll
    for (int jj=0;jj<4;jj++){
        int j = j0 + ty + jj*8;
        hf val = __ushort_as_half((unsigned short)0);
        if (j < nv) val = g_Vh[((size_t)bh*Tv + j)*HDv + hd0+tx];
        t[ty+jj*8][tx] = val;
    }
    __syncthreads();
    #pragma unroll
    for (int jj=0;jj<4;jj++)
        g_Vth[((size_t)bh*HDv + hd0+ty+jj*8)*Tv + j0+tx] = t[tx][ty+jj*8];
}

// ---------------- HMMA GEMM: single-pass fp16 ----------------
#define GLD 40
#define G_STG (2*128*GLD)
#define G_SMEM (2*G_STG*2)

__global__ __launch_bounds__(256,2) void hgemm(
    const hf* __restrict__ Ag, const hf* __restrict__ Wg,
    const float* __restrict__ bias, int mode, float* __restrict__ outf)
{
    extern __shared__ hf gsm[];
    const uint32_t sbase = smem_u32(gsm);
    const int tid = threadIdx.x, lane = tid&31, warp = tid>>5;
    const int g = lane>>2, tig = lane&3;
    const int wm = warp>>2, wn = warp&3;
    const int m0 = blockIdx.y*128, n0 = blockIdx.x*128;
    if (mode == 2 && (m0 & 2047) >= g_nv[m0 >> 11]) return;
    const int lrow = lane&7, ltile = lane>>3;
    const int rowA = (ltile&1)*8 + lrow, kA = (ltile>>1)*8;
    const int rowB = (ltile>>1)*8 + lrow, kB = (ltile&1)*8;

    float acc[4][4][4] = {};

    auto issue = [&](int buf, int k0){
        #pragma unroll
        for (int t=0;t<4;t++){
            int i = tid + t*256, plane = i>>9, w = i&511, row = w>>2, c4 = (w&3)*8;
            const hf* src = plane==0 ? Ag : Wg;
            int grow = (plane==0?m0:n0) + row;
            cp16(sbase + (uint32_t)(buf*G_STG + plane*(128*GLD) + row*GLD + c4)*2,
                 src + (size_t)grow*1024 + k0 + c4);
        }
        CP_COMMIT();
    };

    issue(0, 0);
    for (int kb=0; kb<32; kb++){
        if (kb < 31) issue((kb+1)&1, (kb+1)*32);
        if (kb < 31) CP_WAIT1(); else CP_WAIT0();
        __syncthreads();
        const uint32_t aB = sbase + (uint32_t)((kb&1)*G_STG)*2;
        const uint32_t bB = aB + 128*GLD*2;
        #pragma unroll
        for (int ks=0; ks<2; ks++){
            unsigned ah[4][4], bh[4][2];
            #pragma unroll
            for (int mt=0;mt<4;mt++){
                uint32_t off = (uint32_t)((wm*64 + mt*16 + rowA)*GLD + ks*16 + kA)*2;
                ldsm4(ah[mt], aB + off);
            }
            #pragma unroll
            for (int p2=0;p2<2;p2++){
                unsigned r4[4];
                uint32_t off = (uint32_t)((wn*32 + p2*16 + rowB)*GLD + ks*16 + kB)*2;
                ldsm4(r4, bB + off);
                bh[2*p2][0]=r4[0]; bh[2*p2][1]=r4[1]; bh[2*p2+1][0]=r4[2]; bh[2*p2+1][1]=r4[3];
            }
            #pragma unroll
            for (int mt=0;mt<4;mt++)
                #pragma unroll
                for (int nt=0;nt<4;nt++)
                    mma_f16(acc[mt][nt], ah[mt], bh[nt]);
        }
        __syncthreads();
    }

    #pragma unroll
    for (int mt=0;mt<4;mt++){
        #pragma unroll
        for (int nt=0;nt<4;nt++){
            int r = m0 + wm*64 + mt*16 + g;
            int c = n0 + wn*32 + nt*8 + 2*tig;
            float v00 = acc[mt][nt][0] + bias[c];
            float v01 = acc[mt][nt][1] + bias[c+1];
            float v10 = acc[mt][nt][2] + bias[c];
            float v11 = acc[mt][nt][3] + bias[c+1];
            if (mode == 0){
                *(float2*)(outf + (size_t)r*1024 + c)      = make_float2(v00, v01);
                *(float2*)(outf + (size_t)(r+8)*1024 + c)  = make_float2(v10, v11);
            } else {
                int n2 = c, half = 0;
                if (mode == 2 && c >= 1024){ n2 = c - 1024; half = 1; }
                int h = n2>>6, hd = n2&63;
                #pragma unroll
                for (int rr=0; rr<2; rr++){
                    int m = r + rr*8;
                    int b = m>>11, l = m&2047;
                    float a0 = rr?v10:v00, a1 = rr?v11:v01;
                    size_t base = ((size_t)(b*16 + h)*2048 + l)*64 + hd;
                    if (mode == 1)      *(unsigned*)(g_Qh  + base) = pkh(a0*0.125f, a1*0.125f);
                    else if (!half)     *(unsigned*)(g_Kch + base) = pkh(a0, a1);
                    else                *(unsigned*)(g_Vh  + base) = pkh(a0, a1);
                }
            }
        }
    }
}

// ---------------- HMMA flash attention (all-fp16 single-pass, 64 q/CTA) ----------------
#define ALD 72
#define QH_O 0
#define STG0 (64*ALD)
#define A_STG (2*64*ALD)            // per-stage: K, Vt planes
#define SM_ELEMS (STG0 + 2*A_STG)
#define ATT_SMEM (SM_ELEMS*2)

__global__ __launch_bounds__(128) void hattn()
{
    extern __shared__ hf sm[];
    const uint32_t sbase = smem_u32(sm);
    const int tid = threadIdx.x, lane = tid&31, warp = tid>>5;
    const int g = lane>>2, tig = lane&3;
    const int bh = blockIdx.y, b = bh>>4, h = bh&15, l0 = blockIdx.x*64;
    const int lrow = lane&7, ltile = lane>>3;
    const int rowA = (ltile&1)*8 + lrow, kA = (ltile>>1)*8;
    const int rowB = (ltile>>1)*8 + lrow, kB = (ltile&1)*8;
    const int nv = g_nv[b];
    const int nch = (nv + 63) >> 6;

    auto issueKV = [&](int buf, int t0){
        #pragma unroll
        for (int t=0;t<8;t++){
            int i = tid + t*128, plane = i>>9, w = i&511, row = w>>3, c8 = (w&7)*8;
            const hf* gp;
            if (plane == 0) gp = g_Kch + ((size_t)bh*Tv + t0 + row)*64 + c8;
            else            gp = g_Vth + ((size_t)bh*HDv + row)*Tv + t0 + c8;
            cp16(sbase + (uint32_t)(STG0 + buf*A_STG + plane*(64*ALD) + row*ALD + c8)*2, gp);
        }
        CP_COMMIT();
    };

    // Q [64][64] -> smem
    #pragma unroll
    for (int t=0;t<4;t++){
        int i = tid + t*128, row = i>>3, c8 = (i&7)*8;
        uint4 v = *(const uint4*)(g_Qh + ((size_t)bh*Lv + l0 + row)*64 + c8);
        *(uint4*)(sm + QH_O + row*ALD + c8) = v;
    }
    issueKV(0, 0);
    __syncthreads();

    unsigned qa[4][4];
    #pragma unroll
    for (int kk=0; kk<4; kk++)
        ldsm4(qa[kk], sbase + (uint32_t)(QH_O + (warp*16 + rowA)*ALD + kk*16 + kA)*2);

    float mold[2] = {-INFINITY, -INFINITY};
    float lsum[2] = {0.f, 0.f};
    float o[8][4] = {};

    for (int ci=0; ci<nch; ci++){
        const int t0 = ci*64;
        if (ci < nch-1) issueKV((ci+1)&1, t0+64);
        if (ci < nch-1) CP_WAIT1(); else CP_WAIT0();
        __syncthreads();

        const uint32_t khB = sbase + (uint32_t)(STG0 + (ci&1)*A_STG)*2;
        const uint32_t vhB = khB + 64*ALD*2;
        const int rem = nv - t0;

        float s[8][4] = {};
        #pragma unroll
        for (int kk=0; kk<4; kk++){
            unsigned bhf[8][2];
            #pragma unroll
            for (int p2=0; p2<4; p2++){
                unsigned r4[4];
                uint32_t off = (uint32_t)((p2*16 + rowB)*ALD + kk*16 + kB)*2;
                ldsm4(r4, khB + off);
                bhf[2*p2][0]=r4[0]; bhf[2*p2][1]=r4[1]; bhf[2*p2+1][0]=r4[2]; bhf[2*p2+1][1]=r4[3];
            }
            #pragma unroll
            for (int nt=0; nt<8; nt++)
                mma_f16(s[nt], qa[kk], bhf[nt]);
        }

        float ma = mold[0], mb = mold[1];
        #pragma unroll
        for (int nt=0; nt<8; nt++){
            int c = nt*8 + 2*tig;
            if (c   >= rem){ s[nt][0] = -1e9f; s[nt][2] = -1e9f; }
            if (c+1 >= rem){ s[nt][1] = -1e9f; s[nt][3] = -1e9f; }
            ma = fmaxf(ma, fmaxf(s[nt][0], s[nt][1]));
            mb = fmaxf(mb, fmaxf(s[nt][2], s[nt][3]));
        }
        ma = fmaxf(ma, __shfl_xor_sync(0xffffffffu, ma, 1));
        ma = fmaxf(ma, __shfl_xor_sync(0xffffffffu, ma, 2));
        mb = fmaxf(mb, __shfl_xor_sync(0xffffffffu, mb, 1));
        mb = fmaxf(mb, __shfl_xor_sync(0xffffffffu, mb, 2));

        float aa = __expf(mold[0] - ma), ab = __expf(mold[1] - mb);
        float suma = 0.f, sumb = 0.f;
        #pragma unroll
        for (int nt=0; nt<8; nt++){
            s[nt][0] = __expf(s[nt][0] - ma);
            s[nt][1] = __expf(s[nt][1] - ma);
            s[nt][2] = __expf(s[nt][2] - mb);
            s[nt][3] = __expf(s[nt][3] - mb);
            suma += s[nt][0] + s[nt][1];
            sumb += s[nt][2] + s[nt][3];
        }
        suma += __shfl_xor_sync(0xffffffffu, suma, 1);
        suma += __shfl_xor_sync(0xffffffffu, suma, 2);
        sumb += __shfl_xor_sync(0xffffffffu, sumb, 1);
        sumb += __shfl_xor_sync(0xffffffffu, sumb, 2);
        lsum[0] = lsum[0]*aa + suma;  mold[0] = ma;
        lsum[1] = lsum[1]*ab + sumb;  mold[1] = mb;
        #pragma unroll
        for (int nt=0; nt<8; nt++){
            o[nt][0] *= aa; o[nt][1] *= aa; o[nt][2] *= ab; o[nt][3] *= ab;
        }

        #pragma unroll
        for (int kt=0; kt<4; kt++){
            unsigned pa[4];
            pa[0] = pkh(s[2*kt][0],   s[2*kt][1]);
            pa[1] = pkh(s[2*kt][2],   s[2*kt][3]);
            pa[2] = pkh(s[2*kt+1][0], s[2*kt+1][1]);
            pa[3] = pkh(s[2*kt+1][2], s[2*kt+1][3]);
            #pragma unroll
            for (int p2=0; p2<4; p2++){
                unsigned rv[4];
                uint32_t off = (uint32_t)((p2*16 + rowB)*ALD + kt*16 + kB)*2;
                ldsm4(rv, vhB + off);
                unsigned v0[2] = {rv[0], rv[1]}, v1[2] = {rv[2], rv[3]};
                mma_f16(o[2*p2],   pa, v0);
                mma_f16(o[2*p2+1], pa, v1);
            }
        }
        __syncthreads();
    }

    float inva = 1.0f / lsum[0], invb = 1.0f / lsum[1];
    int ra = l0 + warp*16 + g, rb = ra + 8;
    #pragma unroll
    for (int nt=0; nt<8; nt++){
        int c = h*64 + nt*8 + 2*tig;
        *(unsigned*)(g_Oh + ((size_t)(b*Lv + ra))*Dv + c) = pkh(o[nt][0]*inva, o[nt][1]*inva);
        *(unsigned*)(g_Oh + ((size_t)(b*Lv + rb))*Dv + c) = pkh(o[nt][2]*invb, o[nt][3]*invb);
    }
}

// ---------------- launch ----------------
extern "C" void kernel_launch(void* const* d_in, const int* in_sizes, int n_in,
                              void* d_out, int out_size)
{
    const float* x     = (const float*)d_in[0];
    const float* ctx   = (const float*)d_in[1];
    const int*   cmsk  = (const int*)d_in[2];
    const float* Wq    = (const float*)d_in[3];
    const float* bq    = (const float*)d_in[4];
    const float* Wkv   = (const float*)d_in[5];
    const float* bkv   = (const float*)d_in[6];
    const float* Wproj = (const float*)d_in[7];
    const float* bproj = (const float*)d_in[8];
    float* out         = (float*)d_out;

    hf *xh,*ch,*wqh,*wkh,*wph,*oh;
    cudaGetSymbolAddress((void**)&xh, g_xh);
    cudaGetSymbolAddress((void**)&ch, g_ch);
    cudaGetSymbolAddress((void**)&wqh, g_Wqh);
    cudaGetSymbolAddress((void**)&wkh, g_Wkh);
    cudaGetSymbolAddress((void**)&wph, g_Wph);
    cudaGetSymbolAddress((void**)&oh, g_Oh);

    cudaFuncSetAttribute(hgemm, cudaFuncAttributeMaxDynamicSharedMemorySize, G_SMEM);
    cudaFuncSetAttribute(hattn, cudaFuncAttributeMaxDynamicSharedMemorySize, ATT_SMEM);

    const int NM = Bv*Lv;  // 4096

    mscan<<<Bv, 256>>>(cmsk);                                           // 0
    csplit<<<Bv*Tv, 256>>>(ctx);                                        // 1
    wprep<<<dim3(2*Dv/32, Dv/32), dim3(32,8)>>>(Wkv, wkh, 2*Dv);        // 2
    hgemm<<<dim3(2*Dv/128, NM/128), 256, G_SMEM>>>(ch, wkh, bkv, 2, nullptr);        // 3 (ncu slot)
    fh<<<NM*Dv/256, 256>>>(x, xh, NM*Dv);                               // 4
    wprep<<<dim3(Dv/32, Dv/32), dim3(32,8)>>>(Wq, wqh, Dv);             // 5
    hgemm<<<dim3(Dv/128, NM/128), 256, G_SMEM>>>(xh, wqh, bq, 1, nullptr);           // 6
    wprep<<<dim3(Dv/32, Dv/32), dim3(32,8)>>>(Wproj, wph, Dv);          // 7
    vtrans<<<dim3(Tv/32, HDv/32, BHv), dim3(32,8)>>>();                 // 8
    hattn<<<dim3(Lv/64, BHv), 128, ATT_SMEM>>>();                       // 9
    hgemm<<<dim3(Dv/128, NM/128), 256, G_SMEM>>>(oh, wph, bproj, 0, out);            // 10
}

// round 15
// speedup vs baseline: 2.8618x; 1.0778x over previous
#include <cuda_runtime.h>
#include <cuda_fp16.h>
#include <math.h>
#include <stdint.h>

#define Bv 2
#define Lv 2048
#define Tv 2048
#define Dv 1024
#define Hv 16
#define HDv 64
#define BHv (Bv*Hv)
typedef __half hf;

// ---------------- scratch ----------------
__device__ hf g_xh[Bv*Lv*Dv];
__device__ hf g_ch[Bv*Tv*Dv];                    // compacted ctx rows
__device__ hf g_Wqh[Dv*Dv];                      // [N][K]
__device__ hf g_Wkh[2*Dv*Dv];
__device__ hf g_Wph[Dv*Dv];
__device__ hf g_Qh[BHv*Lv*HDv];                  // (scaled 0.125)
__device__ hf g_Kch[BHv*Tv*HDv];
__device__ hf g_Vh[BHv*Tv*HDv];
__device__ hf g_Vth[BHv*HDv*Tv];
__device__ hf g_Oh[Bv*Lv*Dv];
__device__ int g_vidx[Bv][Tv];
__device__ int g_nv[Bv];

// ---------------- helpers ----------------
__device__ __forceinline__ uint32_t smem_u32(const void* p){
    uint32_t a; asm("{ .reg .u64 t; cvta.to.shared.u64 t, %1; cvt.u32.u64 %0, t; }":"=r"(a):"l"(p)); return a;
}
__device__ __forceinline__ void cp16(uint32_t dst, const void* src){
    asm volatile("cp.async.cg.shared.global [%0], [%1], 16;" :: "r"(dst), "l"(src));
}
#define CP_COMMIT() asm volatile("cp.async.commit_group;")
#define CP_WAIT1()  asm volatile("cp.async.wait_group 1;")
#define CP_WAIT0()  asm volatile("cp.async.wait_group 0;")

__device__ __forceinline__ void ldsm4(unsigned r[4], uint32_t a){
    asm volatile("ldmatrix.sync.aligned.m8n8.x4.shared.b16 {%0,%1,%2,%3}, [%4];"
        : "=r"(r[0]), "=r"(r[1]), "=r"(r[2]), "=r"(r[3]) : "r"(a));
}
__device__ __forceinline__ unsigned short h16(float x){ return __half_as_ushort(__float2half_rn(x)); }
__device__ __forceinline__ unsigned pkh(float a, float b){
    return (unsigned)h16(a) | ((unsigned)h16(b) << 16);
}
__device__ __forceinline__ void mma_f16(float c[4], const unsigned a[4], const unsigned b[2]){
    asm volatile("mma.sync.aligned.m16n8k16.row.col.f32.f16.f16.f32 "
        "{%0,%1,%2,%3}, {%4,%5,%6,%7}, {%8,%9}, {%0,%1,%2,%3};"
        : "+f"(c[0]), "+f"(c[1]), "+f"(c[2]), "+f"(c[3])
        : "r"(a[0]), "r"(a[1]), "r"(a[2]), "r"(a[3]), "r"(b[0]), "r"(b[1]));
}

// ---------------- prep kernels ----------------
__global__ void fh(const float* __restrict__ in, hf* __restrict__ h, int n){
    int i = blockIdx.x*256 + threadIdx.x;
    if (i < n) h[i] = __float2half_rn(in[i]);
}
__global__ void csplit(const float* __restrict__ ctx){
    int row = blockIdx.x;
    int b = row >> 11, j = row & 2047;
    if (j >= g_nv[b]) return;
    const float* p = ctx + ((size_t)b*Tv + g_vidx[b][j])*Dv;
    size_t dst = ((size_t)b*Tv + j)*Dv;
    for (int c = threadIdx.x; c < Dv; c += 256)
        g_ch[dst + c] = __float2half_rn(p[c]);
}
__global__ void wprep(const float* __restrict__ W, hf* __restrict__ th, int N){
    __shared__ float t[32][33];
    int k0 = blockIdx.y*32, n0 = blockIdx.x*32, tx = threadIdx.x, ty = threadIdx.y;
    #pragma unroll
    for (int j=0;j<4;j++) t[ty+j*8][tx] = W[(size_t)(k0+ty+j*8)*N + n0+tx];
    __syncthreads();
    #pragma unroll
    for (int j=0;j<4;j++)
        th[(size_t)(n0+ty+j*8)*Dv + k0+tx] = __float2half_rn(t[tx][ty+j*8]);
}
__global__ void mscan(const int* __restrict__ mask){
    __shared__ int ps[256];
    int b = blockIdx.x, tid = threadIdx.x;
    int v[8]; int cnt = 0;
    #pragma unroll
    for (int i=0;i<8;i++){ v[i] = (mask[b*Tv + tid*8 + i] != 0); cnt += v[i]; }
    ps[tid] = cnt; __syncthreads();
    for (int off=1; off<256; off<<=1){
        int x = (tid >= off) ? ps[tid-off] : 0;
        __syncthreads();
        ps[tid] += x;
        __syncthreads();
    }
    int pre = ps[tid] - cnt;
    #pragma unroll
    for (int i=0;i<8;i++){ if (v[i]) g_vidx[b][pre++] = tid*8 + i; }
    if (tid == 255) g_nv[b] = ps[255];
}
__global__ void vtrans(){
    __shared__ hf t[32][33];
    int bh = blockIdx.z, b = bh>>4;
    int j0 = blockIdx.x*32, hd0 = blockIdx.y*32;
    int tx = threadIdx.x, ty = threadIdx.y;
    int nv = g_nv[b];
    #pragma unroll
    for (int jj=0;jj<4;jj++){
        int j = j0 + ty + jj*8;
        hf val = __ushort_as_half((unsigned short)0);
        if (j < nv) val = g_Vh[((size_t)bh*Tv + j)*HDv + hd0+tx];
        t[ty+jj*8][tx] = val;
    }
    __syncthreads();
    #pragma unroll
    for (int jj=0;jj<4;jj++)
        g_Vth[((size_t)bh*HDv + hd0+ty+jj*8)*Tv + j0+tx] = t[tx][ty+jj*8];
}

// ---------------- HMMA GEMM core (BK=64, 2-stage cp.async) ----------------
#define GLD 72
#define G_STG (2*128*GLD)           // ELEMENTS per stage (A + W planes)
#define G_SMEM_BYTES (2*G_STG*2)    // 2 stages * G_STG elems * 2 B = 73728 B

// body shared by hqkv / hproj; mode: 0 fp32 out, 1 Q, 2 K/V
__device__ __forceinline__ void gemm_body(
    const hf* __restrict__ Ag, const hf* __restrict__ Wg,
    const float* __restrict__ bias, int mode, float* __restrict__ outf,
    int m0, int n0, hf* gsm)
{
    const uint32_t sbase = smem_u32(gsm);
    const int tid = threadIdx.x, lane = tid&31, warp = tid>>5;
    const int g = lane>>2, tig = lane&3;
    const int wm = warp>>2, wn = warp&3;
    const int lrow = lane&7, ltile = lane>>3;
    const int rowA = (ltile&1)*8 + lrow, kA = (ltile>>1)*8;
    const int rowB = (ltile>>1)*8 + lrow, kB = (ltile&1)*8;

    float acc[4][4][4] = {};

    auto issue = [&](int buf, int k0){
        #pragma unroll
        for (int t=0;t<8;t++){
            int i = tid + t*256, plane = i>>10, w = i&1023, row = w>>3, c4 = (w&7)*8;
            const hf* src = plane==0 ? Ag : Wg;
            int grow = (plane==0?m0:n0) + row;
            cp16(sbase + (uint32_t)(buf*G_STG + plane*(128*GLD) + row*GLD + c4)*2,
                 src + (size_t)grow*1024 + k0 + c4);
        }
        CP_COMMIT();
    };

    issue(0, 0);
    for (int kb=0; kb<16; kb++){
        if (kb < 15) issue((kb+1)&1, (kb+1)*64);
        if (kb < 15) CP_WAIT1(); else CP_WAIT0();
        __syncthreads();
        const uint32_t aB = sbase + (uint32_t)((kb&1)*G_STG)*2;
        const uint32_t bB = aB + 128*GLD*2;
        #pragma unroll
        for (int ks=0; ks<4; ks++){
            unsigned ah[4][4], bh[4][2];
            #pragma unroll
            for (int mt=0;mt<4;mt++){
                uint32_t off = (uint32_t)((wm*64 + mt*16 + rowA)*GLD + ks*16 + kA)*2;
                ldsm4(ah[mt], aB + off);
            }
            #pragma unroll
            for (int p2=0;p2<2;p2++){
                unsigned r4[4];
                uint32_t off = (uint32_t)((wn*32 + p2*16 + rowB)*GLD + ks*16 + kB)*2;
                ldsm4(r4, bB + off);
                bh[2*p2][0]=r4[0]; bh[2*p2][1]=r4[1]; bh[2*p2+1][0]=r4[2]; bh[2*p2+1][1]=r4[3];
            }
            #pragma unroll
            for (int mt=0;mt<4;mt++)
                #pragma unroll
                for (int nt=0;nt<4;nt++)
                    mma_f16(acc[mt][nt], ah[mt], bh[nt]);
        }
        __syncthreads();
    }

    #pragma unroll
    for (int mt=0;mt<4;mt++){
        #pragma unroll
        for (int nt=0;nt<4;nt++){
            int r = m0 + wm*64 + mt*16 + g;
            int c = n0 + wn*32 + nt*8 + 2*tig;
            float v00 = acc[mt][nt][0] + bias[c];
            float v01 = acc[mt][nt][1] + bias[c+1];
            float v10 = acc[mt][nt][2] + bias[c];
            float v11 = acc[mt][nt][3] + bias[c+1];
            if (mode == 0){
                *(float2*)(outf + (size_t)r*1024 + c)      = make_float2(v00, v01);
                *(float2*)(outf + (size_t)(r+8)*1024 + c)  = make_float2(v10, v11);
            } else {
                int n2 = c, half = 0;
                if (mode == 2 && c >= 1024){ n2 = c - 1024; half = 1; }
                int h = n2>>6, hd = n2&63;
                #pragma unroll
                for (int rr=0; rr<2; rr++){
                    int m = r + rr*8;
                    int b = m>>11, l = m&2047;
                    float a0 = rr?v10:v00, a1 = rr?v11:v01;
                    size_t base = ((size_t)(b*16 + h)*2048 + l)*64 + hd;
                    if (mode == 1)      *(unsigned*)(g_Qh  + base) = pkh(a0*0.125f, a1*0.125f);
                    else if (!half)     *(unsigned*)(g_Kch + base) = pkh(a0, a1);
                    else                *(unsigned*)(g_Vh  + base) = pkh(a0, a1);
                }
            }
        }
    }
}

// fused Q + KV projection: bx<8 -> Q tile, bx>=8 -> KV tile
__global__ __launch_bounds__(256,2) void hqkv(
    const hf* __restrict__ xh, const hf* __restrict__ chp,
    const hf* __restrict__ wq, const hf* __restrict__ wk,
    const float* __restrict__ bq, const float* __restrict__ bkv)
{
    extern __shared__ hf gsm[];
    int bx = blockIdx.x, m0 = blockIdx.y*128;
    if (bx < 8){
        gemm_body(xh, wq, bq, 1, nullptr, m0, bx*128, gsm);
    } else {
        if ((m0 & 2047) >= g_nv[m0 >> 11]) return;
        gemm_body(chp, wk, bkv, 2, nullptr, m0, (bx-8)*128, gsm);
    }
}
// output projection
__global__ __launch_bounds__(256,2) void hproj(
    const hf* __restrict__ oh, const hf* __restrict__ wp,
    const float* __restrict__ bp, float* __restrict__ outf)
{
    extern __shared__ hf gsm[];
    gemm_body(oh, wp, bp, 0, outf, blockIdx.y*128, blockIdx.x*128, gsm);
}

// ---------------- HMMA flash attention (all-fp16, 64 q/CTA) ----------------
#define ALD 72
#define QH_O 0
#define STG0 (64*ALD)
#define A_STG (2*64*ALD)
#define SM_ELEMS (STG0 + 2*A_STG)
#define ATT_SMEM (SM_ELEMS*2)

__global__ __launch_bounds__(128) void hattn()
{
    extern __shared__ hf sm[];
    const uint32_t sbase = smem_u32(sm);
    const int tid = threadIdx.x, lane = tid&31, warp = tid>>5;
    const int g = lane>>2, tig = lane&3;
    const int bh = blockIdx.y, b = bh>>4, h = bh&15, l0 = blockIdx.x*64;
    const int lrow = lane&7, ltile = lane>>3;
    const int rowA = (ltile&1)*8 + lrow, kA = (ltile>>1)*8;
    const int rowB = (ltile>>1)*8 + lrow, kB = (ltile&1)*8;
    const int nv = g_nv[b];
    const int nch = (nv + 63) >> 6;

    auto issueKV = [&](int buf, int t0){
        #pragma unroll
        for (int t=0;t<8;t++){
            int i = tid + t*128, plane = i>>9, w = i&511, row = w>>3, c8 = (w&7)*8;
            const hf* gp;
            if (plane == 0) gp = g_Kch + ((size_t)bh*Tv + t0 + row)*64 + c8;
            else            gp = g_Vth + ((size_t)bh*HDv + row)*Tv + t0 + c8;
            cp16(sbase + (uint32_t)(STG0 + buf*A_STG + plane*(64*ALD) + row*ALD + c8)*2, gp);
        }
        CP_COMMIT();
    };

    #pragma unroll
    for (int t=0;t<4;t++){
        int i = tid + t*128, row = i>>3, c8 = (i&7)*8;
        uint4 v = *(const uint4*)(g_Qh + ((size_t)bh*Lv + l0 + row)*64 + c8);
        *(uint4*)(sm + QH_O + row*ALD + c8) = v;
    }
    issueKV(0, 0);
    __syncthreads();

    unsigned qa[4][4];
    #pragma unroll
    for (int kk=0; kk<4; kk++)
        ldsm4(qa[kk], sbase + (uint32_t)(QH_O + (warp*16 + rowA)*ALD + kk*16 + kA)*2);

    float mold[2] = {-INFINITY, -INFINITY};
    float lsum[2] = {0.f, 0.f};
    float o[8][4] = {};

    for (int ci=0; ci<nch; ci++){
        const int t0 = ci*64;
        if (ci < nch-1) issueKV((ci+1)&1, t0+64);
        if (ci < nch-1) CP_WAIT1(); else CP_WAIT0();
        __syncthreads();

        const uint32_t khB = sbase + (uint32_t)(STG0 + (ci&1)*A_STG)*2;
        const uint32_t vhB = khB + 64*ALD*2;
        const int rem = nv - t0;

        float s[8][4] = {};
        #pragma unroll
        for (int kk=0; kk<4; kk++){
            unsigned bhf[8][2];
            #pragma unroll
            for (int p2=0; p2<4; p2++){
                unsigned r4[4];
                uint32_t off = (uint32_t)((p2*16 + rowB)*ALD + kk*16 + kB)*2;
                ldsm4(r4, khB + off);
                bhf[2*p2][0]=r4[0]; bhf[2*p2][1]=r4[1]; bhf[2*p2+1][0]=r4[2]; bhf[2*p2+1][1]=r4[3];
            }
            #pragma unroll
            for (int nt=0; nt<8; nt++)
                mma_f16(s[nt], qa[kk], bhf[nt]);
        }

        float ma = mold[0], mb = mold[1];
        #pragma unroll
        for (int nt=0; nt<8; nt++){
            int c = nt*8 + 2*tig;
            if (c   >= rem){ s[nt][0] = -1e9f; s[nt][2] = -1e9f; }
            if (c+1 >= rem){ s[nt][1] = -1e9f; s[nt][3] = -1e9f; }
            ma = fmaxf(ma, fmaxf(s[nt][0], s[nt][1]));
            mb = fmaxf(mb, fmaxf(s[nt][2], s[nt][3]));
        }
        ma = fmaxf(ma, __shfl_xor_sync(0xffffffffu, ma, 1));
        ma = fmaxf(ma, __shfl_xor_sync(0xffffffffu, ma, 2));
        mb = fmaxf(mb, __shfl_xor_sync(0xffffffffu, mb, 1));
        mb = fmaxf(mb, __shfl_xor_sync(0xffffffffu, mb, 2));

        float aa = __expf(mold[0] - ma), ab = __expf(mold[1] - mb);
        float suma = 0.f, sumb = 0.f;
        #pragma unroll
        for (int nt=0; nt<8; nt++){
            s[nt][0] = __expf(s[nt][0] - ma);
            s[nt][1] = __expf(s[nt][1] - ma);
            s[nt][2] = __expf(s[nt][2] - mb);
            s[nt][3] = __expf(s[nt][3] - mb);
            suma += s[nt][0] + s[nt][1];
            sumb += s[nt][2] + s[nt][3];
        }
        suma += __shfl_xor_sync(0xffffffffu, suma, 1);
        suma += __shfl_xor_sync(0xffffffffu, suma, 2);
        sumb += __shfl_xor_sync(0xffffffffu, sumb, 1);
        sumb += __shfl_xor_sync(0xffffffffu, sumb, 2);
        lsum[0] = lsum[0]*aa + suma;  mold[0] = ma;
        lsum[1] = lsum[1]*ab + sumb;  mold[1] = mb;
        #pragma unroll
        for (int nt=0; nt<8; nt++){
            o[nt][0] *= aa; o[nt][1] *= aa; o[nt][2] *= ab; o[nt][3] *= ab;
        }

        #pragma unroll
        for (int kt=0; kt<4; kt++){
            unsigned pa[4];
            pa[0] = pkh(s[2*kt][0],   s[2*kt][1]);
            pa[1] = pkh(s[2*kt][2],   s[2*kt][3]);
            pa[2] = pkh(s[2*kt+1][0], s[2*kt+1][1]);
            pa[3] = pkh(s[2*kt+1][2], s[2*kt+1][3]);
            #pragma unroll
            for (int p2=0; p2<4; p2++){
                unsigned rv[4];
                uint32_t off = (uint32_t)((p2*16 + rowB)*ALD + kt*16 + kB)*2;
                ldsm4(rv, vhB + off);
                unsigned v0[2] = {rv[0], rv[1]}, v1[2] = {rv[2], rv[3]};
                mma_f16(o[2*p2],   pa, v0);
                mma_f16(o[2*p2+1], pa, v1);
            }
        }
        __syncthreads();
    }

    float inva = 1.0f / lsum[0], invb = 1.0f / lsum[1];
    int ra = l0 + warp*16 + g, rb = ra + 8;
    #pragma unroll
    for (int nt=0; nt<8; nt++){
        int c = h*64 + nt*8 + 2*tig;
        *(unsigned*)(g_Oh + ((size_t)(b*Lv + ra))*Dv + c) = pkh(o[nt][0]*inva, o[nt][1]*inva);
        *(unsigned*)(g_Oh + ((size_t)(b*Lv + rb))*Dv + c) = pkh(o[nt][2]*invb, o[nt][3]*invb);
    }
}

// ---------------- launch ----------------
extern "C" void kernel_launch(void* const* d_in, const int* in_sizes, int n_in,
                              void* d_out, int out_size)
{
    const float* x     = (const float*)d_in[0];
    const float* ctx   = (const float*)d_in[1];
    const int*   cmsk  = (const int*)d_in[2];
    const float* Wq    = (const float*)d_in[3];
    const float* bq    = (const float*)d_in[4];
    const float* Wkv   = (const float*)d_in[5];
    const float* bkv   = (const float*)d_in[6];
    const float* Wproj = (const float*)d_in[7];
    const float* bproj = (const float*)d_in[8];
    float* out         = (float*)d_out;

    hf *xh,*ch,*wqh,*wkh,*wph,*oh;
    cudaGetSymbolAddress((void**)&xh, g_xh);
    cudaGetSymbolAddress((void**)&ch, g_ch);
    cudaGetSymbolAddress((void**)&wqh, g_Wqh);
    cudaGetSymbolAddress((void**)&wkh, g_Wkh);
    cudaGetSymbolAddress((void**)&wph, g_Wph);
    cudaGetSymbolAddress((void**)&oh, g_Oh);

    cudaFuncSetAttribute(hqkv,  cudaFuncAttributeMaxDynamicSharedMemorySize, G_SMEM_BYTES);
    cudaFuncSetAttribute(hproj, cudaFuncAttributeMaxDynamicSharedMemorySize, G_SMEM_BYTES);
    cudaFuncSetAttribute(hattn, cudaFuncAttributeMaxDynamicSharedMemorySize, ATT_SMEM);

    const int NM = Bv*Lv;  // 4096

    mscan<<<Bv, 256>>>(cmsk);                                           // 0
    csplit<<<Bv*Tv, 256>>>(ctx);                                        // 1
    fh<<<NM*Dv/256, 256>>>(x, xh, NM*Dv);                               // 2
    wprep<<<dim3(2*Dv/32, Dv/32), dim3(32,8)>>>(Wkv, wkh, 2*Dv);        // 3
    wprep<<<dim3(Dv/32, Dv/32), dim3(32,8)>>>(Wq, wqh, Dv);             // 4
    hqkv<<<dim3(24, NM/128), 256, G_SMEM_BYTES>>>(xh, ch, wqh, wkh, bq, bkv); // 5
    wprep<<<dim3(Dv/32, Dv/32), dim3(32,8)>>>(Wproj, wph, Dv);          // 6
    vtrans<<<dim3(Tv/32, HDv/32, BHv), dim3(32,8)>>>();                 // 7
    hattn<<<dim3(Lv/64, BHv), 128, ATT_SMEM>>>();                       // 8
    hproj<<<dim3(Dv/128, NM/128), 256, G_SMEM_BYTES>>>(oh, wph, bproj, out);  // 9
}

// round 16
// speedup vs baseline: 3.0800x; 1.0763x over previous
#include <cuda_runtime.h>
#include <cuda_fp16.h>
#include <math.h>
#include <stdint.h>

#define Bv 2
#define Lv 2048
#define Tv 2048
#define Dv 1024
#define Hv 16
#define HDv 64
#define BHv (Bv*Hv)
typedef __half hf;

// ---------------- scratch ----------------
__device__ hf g_xh[Bv*Lv*Dv];
__device__ hf g_ch[Bv*Tv*Dv];                    // compacted ctx rows
__device__ hf g_Wqh[Dv*Dv];                      // [N][K]
__device__ hf g_Wkh[2*Dv*Dv];
__device__ hf g_Wph[Dv*Dv];
__device__ hf g_Qh[BHv*Lv*HDv];                  // (scaled 0.125)
__device__ hf g_Kch[BHv*Tv*HDv];                 // compacted K [bh][j][hd]
__device__ hf g_Vh[BHv*Tv*HDv];                  // compacted V [bh][j][hd] (tail = 0)
__device__ hf g_Oh[Bv*Lv*Dv];
__device__ int g_vidx[Bv][Tv];
__device__ int g_nv[Bv];

// ---------------- helpers ----------------
__device__ __forceinline__ uint32_t smem_u32(const void* p){
    uint32_t a; asm("{ .reg .u64 t; cvta.to.shared.u64 t, %1; cvt.u32.u64 %0, t; }":"=r"(a):"l"(p)); return a;
}
__device__ __forceinline__ void cp16(uint32_t dst, const void* src){
    asm volatile("cp.async.cg.shared.global [%0], [%1], 16;" :: "r"(dst), "l"(src));
}
#define CP_COMMIT() asm volatile("cp.async.commit_group;")
#define CP_WAIT1()  asm volatile("cp.async.wait_group 1;")
#define CP_WAIT0()  asm volatile("cp.async.wait_group 0;")

__device__ __forceinline__ void ldsm4(unsigned r[4], uint32_t a){
    asm volatile("ldmatrix.sync.aligned.m8n8.x4.shared.b16 {%0,%1,%2,%3}, [%4];"
        : "=r"(r[0]), "=r"(r[1]), "=r"(r[2]), "=r"(r[3]) : "r"(a));
}
__device__ __forceinline__ void ldsm4t(unsigned r[4], uint32_t a){
    asm volatile("ldmatrix.sync.aligned.m8n8.x4.trans.shared.b16 {%0,%1,%2,%3}, [%4];"
        : "=r"(r[0]), "=r"(r[1]), "=r"(r[2]), "=r"(r[3]) : "r"(a));
}
__device__ __forceinline__ unsigned short h16(float x){ return __half_as_ushort(__float2half_rn(x)); }
__device__ __forceinline__ unsigned pkh(float a, float b){
    return (unsigned)h16(a) | ((unsigned)h16(b) << 16);
}
__device__ __forceinline__ void mma_f16(float c[4], const unsigned a[4], const unsigned b[2]){
    asm volatile("mma.sync.aligned.m16n8k16.row.col.f32.f16.f16.f32 "
        "{%0,%1,%2,%3}, {%4,%5,%6,%7}, {%8,%9}, {%0,%1,%2,%3};"
        : "+f"(c[0]), "+f"(c[1]), "+f"(c[2]), "+f"(c[3])
        : "r"(a[0]), "r"(a[1]), "r"(a[2]), "r"(a[3]), "r"(b[0]), "r"(b[1]));
}

// ---------------- prep kernels ----------------
__global__ void mscan(const int* __restrict__ mask){
    __shared__ int ps[256];
    int b = blockIdx.x, tid = threadIdx.x;
    int v[8]; int cnt = 0;
    #pragma unroll
    for (int i=0;i<8;i++){ v[i] = (mask[b*Tv + tid*8 + i] != 0); cnt += v[i]; }
    ps[tid] = cnt; __syncthreads();
    for (int off=1; off<256; off<<=1){
        int x = (tid >= off) ? ps[tid-off] : 0;
        __syncthreads();
        ps[tid] += x;
        __syncthreads();
    }
    int pre = ps[tid] - cnt;
    #pragma unroll
    for (int i=0;i<8;i++){ if (v[i]) g_vidx[b][pre++] = tid*8 + i; }
    if (tid == 255) g_nv[b] = ps[255];
}
// fused: x fp32->fp16 rows (bx<4096) + ctx compacting gather (bx>=4096)
__global__ void prep_act(const float* __restrict__ x, const float* __restrict__ ctx){
    int bx = blockIdx.x;
    if (bx < Bv*Lv){
        const float* p = x + (size_t)bx*Dv;
        size_t dst = (size_t)bx*Dv;
        for (int c = threadIdx.x; c < Dv; c += 256)
            g_xh[dst + c] = __float2half_rn(p[c]);
    } else {
        int row = bx - Bv*Lv;
        int b = row >> 11, j = row & 2047;
        if (j >= g_nv[b]) return;
        const float* p = ctx + ((size_t)b*Tv + g_vidx[b][j])*Dv;
        size_t dst = ((size_t)b*Tv + j)*Dv;
        for (int c = threadIdx.x; c < Dv; c += 256)
            g_ch[dst + c] = __float2half_rn(p[c]);
    }
}
// fused transpose+convert of all three weights; z: 0=Wq, 1/2=Wkv halves, 3=Wproj
__global__ void wprep_all(const float* __restrict__ Wq, const float* __restrict__ Wkv,
                          const float* __restrict__ Wp){
    __shared__ float t[32][33];
    int z = blockIdx.z;
    const float* W; hf* th; int N; int noff = 0;
    if (z == 0){ W = Wq;  th = g_Wqh; N = 1024; }
    else if (z == 3){ W = Wp; th = g_Wph; N = 1024; }
    else { W = Wkv; th = g_Wkh; N = 2048; noff = (z-1)*1024; }
    int k0 = blockIdx.y*32, n0 = blockIdx.x*32 + noff;
    int tx = threadIdx.x, ty = threadIdx.y;
    #pragma unroll
    for (int j=0;j<4;j++) t[ty+j*8][tx] = W[(size_t)(k0+ty+j*8)*N + n0+tx];
    __syncthreads();
    #pragma unroll
    for (int j=0;j<4;j++)
        th[(size_t)(n0+ty+j*8)*Dv + k0+tx] = __float2half_rn(t[tx][ty+j*8]);
}

// ---------------- HMMA GEMM core (BK=64, 2-stage cp.async) ----------------
#define GLD 72
#define G_STG (2*128*GLD)           // ELEMENTS per stage (A + W planes)
#define G_SMEM_BYTES (2*G_STG*2)    // 73728 B

__device__ __forceinline__ void gemm_body(
    const hf* __restrict__ Ag, const hf* __restrict__ Wg,
    const float* __restrict__ bias, int mode, float* __restrict__ outf,
    int m0, int n0, hf* gsm)
{
    const uint32_t sbase = smem_u32(gsm);
    const int tid = threadIdx.x, lane = tid&31, warp = tid>>5;
    const int g = lane>>2, tig = lane&3;
    const int wm = warp>>2, wn = warp&3;
    const int lrow = lane&7, ltile = lane>>3;
    const int rowA = (ltile&1)*8 + lrow, kA = (ltile>>1)*8;
    const int rowB = (ltile>>1)*8 + lrow, kB = (ltile&1)*8;

    float acc[4][4][4] = {};

    auto issue = [&](int buf, int k0){
        #pragma unroll
        for (int t=0;t<8;t++){
            int i = tid + t*256, plane = i>>10, w = i&1023, row = w>>3, c4 = (w&7)*8;
            const hf* src = plane==0 ? Ag : Wg;
            int grow = (plane==0?m0:n0) + row;
            cp16(sbase + (uint32_t)(buf*G_STG + plane*(128*GLD) + row*GLD + c4)*2,
                 src + (size_t)grow*1024 + k0 + c4);
        }
        CP_COMMIT();
    };

    issue(0, 0);
    for (int kb=0; kb<16; kb++){
        if (kb < 15) issue((kb+1)&1, (kb+1)*64);
        if (kb < 15) CP_WAIT1(); else CP_WAIT0();
        __syncthreads();
        const uint32_t aB = sbase + (uint32_t)((kb&1)*G_STG)*2;
        const uint32_t bB = aB + 128*GLD*2;
        #pragma unroll
        for (int ks=0; ks<4; ks++){
            unsigned ah[4][4], bh[4][2];
            #pragma unroll
            for (int mt=0;mt<4;mt++){
                uint32_t off = (uint32_t)((wm*64 + mt*16 + rowA)*GLD + ks*16 + kA)*2;
                ldsm4(ah[mt], aB + off);
            }
            #pragma unroll
            for (int p2=0;p2<2;p2++){
                unsigned r4[4];
                uint32_t off = (uint32_t)((wn*32 + p2*16 + rowB)*GLD + ks*16 + kB)*2;
                ldsm4(r4, bB + off);
                bh[2*p2][0]=r4[0]; bh[2*p2][1]=r4[1]; bh[2*p2+1][0]=r4[2]; bh[2*p2+1][1]=r4[3];
            }
            #pragma unroll
            for (int mt=0;mt<4;mt++)
                #pragma unroll
                for (int nt=0;nt<4;nt++)
                    mma_f16(acc[mt][nt], ah[mt], bh[nt]);
        }
        __syncthreads();
    }

    #pragma unroll
    for (int mt=0;mt<4;mt++){
        #pragma unroll
        for (int nt=0;nt<4;nt++){
            int r = m0 + wm*64 + mt*16 + g;
            int c = n0 + wn*32 + nt*8 + 2*tig;
            float v00 = acc[mt][nt][0] + bias[c];
            float v01 = acc[mt][nt][1] + bias[c+1];
            float v10 = acc[mt][nt][2] + bias[c];
            float v11 = acc[mt][nt][3] + bias[c+1];
            if (mode == 0){
                *(float2*)(outf + (size_t)r*1024 + c)      = make_float2(v00, v01);
                *(float2*)(outf + (size_t)(r+8)*1024 + c)  = make_float2(v10, v11);
            } else {
                int n2 = c, half = 0;
                if (mode == 2 && c >= 1024){ n2 = c - 1024; half = 1; }
                int h = n2>>6, hd = n2&63;
                #pragma unroll
                for (int rr=0; rr<2; rr++){
                    int m = r + rr*8;
                    int b = m>>11, l = m&2047;
                    float a0 = rr?v10:v00, a1 = rr?v11:v01;
                    size_t base = ((size_t)(b*16 + h)*2048 + l)*64 + hd;
                    if (mode == 1)      *(unsigned*)(g_Qh  + base) = pkh(a0*0.125f, a1*0.125f);
                    else if (!half)     *(unsigned*)(g_Kch + base) = pkh(a0, a1);
                    else                *(unsigned*)(g_Vh  + base) = pkh(a0, a1);
                }
            }
        }
    }
}

// fused Q + KV projection: bx<8 -> Q tile, bx>=8 -> KV tile
__global__ __launch_bounds__(256,2) void hqkv(
    const hf* __restrict__ xh, const hf* __restrict__ chp,
    const hf* __restrict__ wq, const hf* __restrict__ wk,
    const float* __restrict__ bq, const float* __restrict__ bkv)
{
    extern __shared__ hf gsm[];
    int bx = blockIdx.x, m0 = blockIdx.y*128;
    if (bx < 8){
        gemm_body(xh, wq, bq, 1, nullptr, m0, bx*128, gsm);
    } else {
        if ((m0 & 2047) >= g_nv[m0 >> 11]) return;
        gemm_body(chp, wk, bkv, 2, nullptr, m0, (bx-8)*128, gsm);
    }
}
// output projection
__global__ __launch_bounds__(256,2) void hproj(
    const hf* __restrict__ oh, const hf* __restrict__ wp,
    const float* __restrict__ bp, float* __restrict__ outf)
{
    extern __shared__ hf gsm[];
    gemm_body(oh, wp, bp, 0, outf, blockIdx.y*128, blockIdx.x*128, gsm);
}

// ---------------- HMMA flash attention (fp16, V via ldmatrix.trans) ----------------
#define ALD 72
#define QH_O 0
#define STG0 (64*ALD)
#define A_STG (2*64*ALD)            // per-stage: K, V planes (both [j][hd])
#define SM_ELEMS (STG0 + 2*A_STG)
#define ATT_SMEM (SM_ELEMS*2)

__global__ __launch_bounds__(128) void hattn()
{
    extern __shared__ hf sm[];
    const uint32_t sbase = smem_u32(sm);
    const int tid = threadIdx.x, lane = tid&31, warp = tid>>5;
    const int g = lane>>2, tig = lane&3;
    const int bh = blockIdx.y, b = bh>>4, h = bh&15, l0 = blockIdx.x*64;
    const int lrow = lane&7, ltile = lane>>3;
    const int rowA = (ltile&1)*8 + lrow, kA = (ltile>>1)*8;
    const int rowB = (ltile>>1)*8 + lrow, kB = (ltile&1)*8;
    const int nv = g_nv[b];
    const int nch = (nv + 63) >> 6;

    auto issueKV = [&](int buf, int t0){
        #pragma unroll
        for (int t=0;t<8;t++){
            int i = tid + t*128, plane = i>>9, w = i&511, row = w>>3, c8 = (w&7)*8;
            const hf* gp = (plane == 0)
                ? g_Kch + ((size_t)bh*Tv + t0 + row)*64 + c8
                : g_Vh  + ((size_t)bh*Tv + t0 + row)*64 + c8;
            cp16(sbase + (uint32_t)(STG0 + buf*A_STG + plane*(64*ALD) + row*ALD + c8)*2, gp);
        }
        CP_COMMIT();
    };

    #pragma unroll
    for (int t=0;t<4;t++){
        int i = tid + t*128, row = i>>3, c8 = (i&7)*8;
        uint4 v = *(const uint4*)(g_Qh + ((size_t)bh*Lv + l0 + row)*64 + c8);
        *(uint4*)(sm + QH_O + row*ALD + c8) = v;
    }
    issueKV(0, 0);
    __syncthreads();

    unsigned qa[4][4];
    #pragma unroll
    for (int kk=0; kk<4; kk++)
        ldsm4(qa[kk], sbase + (uint32_t)(QH_O + (warp*16 + rowA)*ALD + kk*16 + kA)*2);

    float mold[2] = {-INFINITY, -INFINITY};
    float lsum[2] = {0.f, 0.f};
    float o[8][4] = {};

    for (int ci=0; ci<nch; ci++){
        const int t0 = ci*64;
        if (ci < nch-1) issueKV((ci+1)&1, t0+64);
        if (ci < nch-1) CP_WAIT1(); else CP_WAIT0();
        __syncthreads();

        const uint32_t khB = sbase + (uint32_t)(STG0 + (ci&1)*A_STG)*2;
        const uint32_t vhB = khB + 64*ALD*2;
        const int rem = nv - t0;

        float s[8][4] = {};
        #pragma unroll
        for (int kk=0; kk<4; kk++){
            unsigned bhf[8][2];
            #pragma unroll
            for (int p2=0; p2<4; p2++){
                unsigned r4[4];
                uint32_t off = (uint32_t)((p2*16 + rowB)*ALD + kk*16 + kB)*2;
                ldsm4(r4, khB + off);
                bhf[2*p2][0]=r4[0]; bhf[2*p2][1]=r4[1]; bhf[2*p2+1][0]=r4[2]; bhf[2*p2+1][1]=r4[3];
            }
            #pragma unroll
            for (int nt=0; nt<8; nt++)
                mma_f16(s[nt], qa[kk], bhf[nt]);
        }

        float ma = mold[0], mb = mold[1];
        #pragma unroll
        for (int nt=0; nt<8; nt++){
            int c = nt*8 + 2*tig;
            if (c   >= rem){ s[nt][0] = -1e9f; s[nt][2] = -1e9f; }
            if (c+1 >= rem){ s[nt][1] = -1e9f; s[nt][3] = -1e9f; }
            ma = fmaxf(ma, fmaxf(s[nt][0], s[nt][1]));
            mb = fmaxf(mb, fmaxf(s[nt][2], s[nt][3]));
        }
        ma = fmaxf(ma, __shfl_xor_sync(0xffffffffu, ma, 1));
        ma = fmaxf(ma, __shfl_xor_sync(0xffffffffu, ma, 2));
        mb = fmaxf(mb, __shfl_xor_sync(0xffffffffu, mb, 1));
        mb = fmaxf(mb, __shfl_xor_sync(0xffffffffu, mb, 2));

        float aa = __expf(mold[0] - ma), ab = __expf(mold[1] - mb);
        float suma = 0.f, sumb = 0.f;
        #pragma unroll
        for (int nt=0; nt<8; nt++){
            s[nt][0] = __expf(s[nt][0] - ma);
            s[nt][1] = __expf(s[nt][1] - ma);
            s[nt][2] = __expf(s[nt][2] - mb);
            s[nt][3] = __expf(s[nt][3] - mb);
            suma += s[nt][0] + s[nt][1];
            sumb += s[nt][2] + s[nt][3];
        }
        suma += __shfl_xor_sync(0xffffffffu, suma, 1);
        suma += __shfl_xor_sync(0xffffffffu, suma, 2);
        sumb += __shfl_xor_sync(0xffffffffu, sumb, 1);
        sumb += __shfl_xor_sync(0xffffffffu, sumb, 2);
        lsum[0] = lsum[0]*aa + suma;  mold[0] = ma;
        lsum[1] = lsum[1]*ab + sumb;  mold[1] = mb;
        #pragma unroll
        for (int nt=0; nt<8; nt++){
            o[nt][0] *= aa; o[nt][1] *= aa; o[nt][2] *= ab; o[nt][3] *= ab;
        }

        // PV: V [j][hd] in smem, transposed to B-fragments by ldmatrix.trans.
        // addr rows = j (k dim), cols = hd (n dim); tile order matches v0/v1 use.
        #pragma unroll
        for (int kt=0; kt<4; kt++){
            unsigned pa[4];
            pa[0] = pkh(s[2*kt][0],   s[2*kt][1]);
            pa[1] = pkh(s[2*kt][2],   s[2*kt][3]);
            pa[2] = pkh(s[2*kt+1][0], s[2*kt+1][1]);
            pa[3] = pkh(s[2*kt+1][2], s[2*kt+1][3]);
            #pragma unroll
            for (int p2=0; p2<4; p2++){
                unsigned rv[4];
                uint32_t off = (uint32_t)((kt*16 + rowA)*ALD + p2*16 + kA)*2;
                ldsm4t(rv, vhB + off);
                unsigned v0[2] = {rv[0], rv[1]}, v1[2] = {rv[2], rv[3]};
                mma_f16(o[2*p2],   pa, v0);
                mma_f16(o[2*p2+1], pa, v1);
            }
        }
        __syncthreads();
    }

    float inva = 1.0f / lsum[0], invb = 1.0f / lsum[1];
    int ra = l0 + warp*16 + g, rb = ra + 8;
    #pragma unroll
    for (int nt=0; nt<8; nt++){
        int c = h*64 + nt*8 + 2*tig;
        *(unsigned*)(g_Oh + ((size_t)(b*Lv + ra))*Dv + c) = pkh(o[nt][0]*inva, o[nt][1]*inva);
        *(unsigned*)(g_Oh + ((size_t)(b*Lv + rb))*Dv + c) = pkh(o[nt][2]*invb, o[nt][3]*invb);
    }
}

// ---------------- launch ----------------
extern "C" void kernel_launch(void* const* d_in, const int* in_sizes, int n_in,
                              void* d_out, int out_size)
{
    const float* x     = (const float*)d_in[0];
    const float* ctx   = (const float*)d_in[1];
    const int*   cmsk  = (const int*)d_in[2];
    const float* Wq    = (const float*)d_in[3];
    const float* bq    = (const float*)d_in[4];
    const float* Wkv   = (const float*)d_in[5];
    const float* bkv   = (const float*)d_in[6];
    const float* Wproj = (const float*)d_in[7];
    const float* bproj = (const float*)d_in[8];
    float* out         = (float*)d_out;

    hf *xh,*ch,*wqh,*wkh,*wph,*oh;
    cudaGetSymbolAddress((void**)&xh, g_xh);
    cudaGetSymbolAddress((void**)&ch, g_ch);
    cudaGetSymbolAddress((void**)&wqh, g_Wqh);
    cudaGetSymbolAddress((void**)&wkh, g_Wkh);
    cudaGetSymbolAddress((void**)&wph, g_Wph);
    cudaGetSymbolAddress((void**)&oh, g_Oh);

    cudaFuncSetAttribute(hqkv,  cudaFuncAttributeMaxDynamicSharedMemorySize, G_SMEM_BYTES);
    cudaFuncSetAttribute(hproj, cudaFuncAttributeMaxDynamicSharedMemorySize, G_SMEM_BYTES);
    cudaFuncSetAttribute(hattn, cudaFuncAttributeMaxDynamicSharedMemorySize, ATT_SMEM);

    const int NM = Bv*Lv;  // 4096

    mscan<<<Bv, 256>>>(cmsk);                                            // 0
    prep_act<<<2*NM, 256>>>(x, ctx);                                     // 1
    wprep_all<<<dim3(32, 32, 4), dim3(32,8)>>>(Wq, Wkv, Wproj);          // 2
    hqkv<<<dim3(24, NM/128), 256, G_SMEM_BYTES>>>(xh, ch, wqh, wkh, bq, bkv); // 3 (ncu slot)
    hattn<<<dim3(Lv/64, BHv), 128, ATT_SMEM>>>();                        // 4
    hproj<<<dim3(Dv/128, NM/128), 256, G_SMEM_BYTES>>>(oh, wph, bproj, out);  // 5
}

// round 17
// speedup vs baseline: 3.1429x; 1.0204x over previous
#include <cuda_runtime.h>
#include <cuda_fp16.h>
#include <math.h>
#include <stdint.h>

#define Bv 2
#define Lv 2048
#define Tv 2048
#define Dv 1024
#define Hv 16
#define HDv 64
#define BHv (Bv*Hv)
typedef __half hf;

// ---------------- scratch ----------------
__device__ hf g_xh[Bv*Lv*Dv];
__device__ hf g_ch[Bv*Tv*Dv];                    // compacted ctx rows
__device__ hf g_Wqh[Dv*Dv];                      // [N][K]
__device__ hf g_Wkh[2*Dv*Dv];
__device__ hf g_Wph[Dv*Dv];
__device__ hf g_Qh[BHv*Lv*HDv];                  // (scaled 0.125)
__device__ hf g_Kch[BHv*Tv*HDv];                 // compacted K [bh][j][hd]
__device__ hf g_Vh[BHv*Tv*HDv];                  // compacted V [bh][j][hd] (tail = 0)
__device__ hf g_Oh[Bv*Lv*Dv];
__device__ int g_vidx[Bv][Tv];
__device__ int g_nv[Bv];
__device__ int g_tilec;                          // persistent-GEMM tile counter

// ---------------- helpers ----------------
__device__ __forceinline__ uint32_t smem_u32(const void* p){
    uint32_t a; asm("{ .reg .u64 t; cvta.to.shared.u64 t, %1; cvt.u32.u64 %0, t; }":"=r"(a):"l"(p)); return a;
}
__device__ __forceinline__ void cp16(uint32_t dst, const void* src){
    asm volatile("cp.async.cg.shared.global [%0], [%1], 16;" :: "r"(dst), "l"(src));
}
#define CP_COMMIT() asm volatile("cp.async.commit_group;")
#define CP_WAIT1()  asm volatile("cp.async.wait_group 1;")
#define CP_WAIT0()  asm volatile("cp.async.wait_group 0;")

__device__ __forceinline__ void ldsm4(unsigned r[4], uint32_t a){
    asm volatile("ldmatrix.sync.aligned.m8n8.x4.shared.b16 {%0,%1,%2,%3}, [%4];"
        : "=r"(r[0]), "=r"(r[1]), "=r"(r[2]), "=r"(r[3]) : "r"(a));
}
__device__ __forceinline__ void ldsm4t(unsigned r[4], uint32_t a){
    asm volatile("ldmatrix.sync.aligned.m8n8.x4.trans.shared.b16 {%0,%1,%2,%3}, [%4];"
        : "=r"(r[0]), "=r"(r[1]), "=r"(r[2]), "=r"(r[3]) : "r"(a));
}
__device__ __forceinline__ unsigned short h16(float x){ return __half_as_ushort(__float2half_rn(x)); }
__device__ __forceinline__ unsigned pkh(float a, float b){
    return (unsigned)h16(a) | ((unsigned)h16(b) << 16);
}
__device__ __forceinline__ void mma_f16(float c[4], const unsigned a[4], const unsigned b[2]){
    asm volatile("mma.sync.aligned.m16n8k16.row.col.f32.f16.f16.f32 "
        "{%0,%1,%2,%3}, {%4,%5,%6,%7}, {%8,%9}, {%0,%1,%2,%3};"
        : "+f"(c[0]), "+f"(c[1]), "+f"(c[2]), "+f"(c[3])
        : "r"(a[0]), "r"(a[1]), "r"(a[2]), "r"(a[3]), "r"(b[0]), "r"(b[1]));
}

// ---------------- prep kernels ----------------
__global__ void mscan(const int* __restrict__ mask){
    __shared__ int ps[256];
    int b = blockIdx.x, tid = threadIdx.x;
    if (b == 0 && tid == 0) g_tilec = 0;     // reset persistent-tile counter
    int v[8]; int cnt = 0;
    #pragma unroll
    for (int i=0;i<8;i++){ v[i] = (mask[b*Tv + tid*8 + i] != 0); cnt += v[i]; }
    ps[tid] = cnt; __syncthreads();
    for (int off=1; off<256; off<<=1){
        int x = (tid >= off) ? ps[tid-off] : 0;
        __syncthreads();
        ps[tid] += x;
        __syncthreads();
    }
    int pre = ps[tid] - cnt;
    #pragma unroll
    for (int i=0;i<8;i++){ if (v[i]) g_vidx[b][pre++] = tid*8 + i; }
    if (tid == 255) g_nv[b] = ps[255];
}
// fused prep: bx<4096 x-convert; 4096..8191 ctx gather; 8192+ weight transpose
__global__ void prep_all(const float* __restrict__ x, const float* __restrict__ ctx,
                         const float* __restrict__ Wq, const float* __restrict__ Wkv,
                         const float* __restrict__ Wp){
    int bx = blockIdx.x, tid = threadIdx.x;
    if (bx < Bv*Lv){
        const float* p = x + (size_t)bx*Dv;
        size_t dst = (size_t)bx*Dv;
        for (int c = tid; c < Dv; c += 256)
            g_xh[dst + c] = __float2half_rn(p[c]);
    } else if (bx < 2*Bv*Lv){
        int row = bx - Bv*Lv;
        int b = row >> 11, j = row & 2047;
        if (j >= g_nv[b]) return;
        const float* p = ctx + ((size_t)b*Tv + g_vidx[b][j])*Dv;
        size_t dst = ((size_t)b*Tv + j)*Dv;
        for (int c = tid; c < Dv; c += 256)
            g_ch[dst + c] = __float2half_rn(p[c]);
    } else {
        __shared__ float t[32][33];
        int w = bx - 2*Bv*Lv;           // 0..4095
        int z = w >> 10, rem = w & 1023;
        int wx = rem & 31, wy = rem >> 5;
        const float* W; hf* th; int N; int noff = 0;
        if (z == 0){ W = Wq;  th = g_Wqh; N = 1024; }
        else if (z == 3){ W = Wp; th = g_Wph; N = 1024; }
        else { W = Wkv; th = g_Wkh; N = 2048; noff = (z-1)*1024; }
        int k0 = wy*32, n0 = wx*32 + noff;
        int tx = tid & 31, ty = tid >> 5;
        #pragma unroll
        for (int j=0;j<4;j++) t[ty+j*8][tx] = W[(size_t)(k0+ty+j*8)*N + n0+tx];
        __syncthreads();
        #pragma unroll
        for (int j=0;j<4;j++)
            th[(size_t)(n0+ty+j*8)*Dv + k0+tx] = __float2half_rn(t[tx][ty+j*8]);
    }
}

// ---------------- HMMA GEMM core (BK=64, 3-stage cp.async, single sync) ----------------
#define GLD 72
#define G_STG (2*128*GLD)            // ELEMENTS per stage (A + W planes)
#define G_SMEM_BYTES (3*G_STG*2)     // 110592 B

__device__ __forceinline__ void gemm_body(
    const hf* __restrict__ Ag, const hf* __restrict__ Wg,
    const float* __restrict__ bias, int mode, float* __restrict__ outf,
    int m0, int n0, hf* gsm)
{
    const uint32_t sbase = smem_u32(gsm);
    const int tid = threadIdx.x, lane = tid&31, warp = tid>>5;
    const int g = lane>>2, tig = lane&3;
    const int wm = warp>>2, wn = warp&3;
    const int lrow = lane&7, ltile = lane>>3;
    const int rowA = (ltile&1)*8 + lrow, kA = (ltile>>1)*8;
    const int rowB = (ltile>>1)*8 + lrow, kB = (ltile&1)*8;

    float acc[4][4][4] = {};

    auto issue = [&](int buf, int k0){
        #pragma unroll
        for (int t=0;t<8;t++){
            int i = tid + t*256, plane = i>>10, w = i&1023, row = w>>3, c4 = (w&7)*8;
            const hf* src = plane==0 ? Ag : Wg;
            int grow = (plane==0?m0:n0) + row;
            cp16(sbase + (uint32_t)(buf*G_STG + plane*(128*GLD) + row*GLD + c4)*2,
                 src + (size_t)grow*1024 + k0 + c4);
        }
        CP_COMMIT();
    };

    issue(0, 0);
    issue(1, 64);
    for (int kb=0; kb<16; kb++){
        if (kb < 15) CP_WAIT1(); else CP_WAIT0();
        __syncthreads();                      // data visible + WAR guard for end-issue
        const uint32_t aB = sbase + (uint32_t)((kb%3)*G_STG)*2;
        const uint32_t bB = aB + 128*GLD*2;
        #pragma unroll
        for (int ks=0; ks<4; ks++){
            unsigned ah[4][4], bh[4][2];
            #pragma unroll
            for (int mt=0;mt<4;mt++){
                uint32_t off = (uint32_t)((wm*64 + mt*16 + rowA)*GLD + ks*16 + kA)*2;
                ldsm4(ah[mt], aB + off);
            }
            #pragma unroll
            for (int p2=0;p2<2;p2++){
                unsigned r4[4];
                uint32_t off = (uint32_t)((wn*32 + p2*16 + rowB)*GLD + ks*16 + kB)*2;
                ldsm4(r4, bB + off);
                bh[2*p2][0]=r4[0]; bh[2*p2][1]=r4[1]; bh[2*p2+1][0]=r4[2]; bh[2*p2+1][1]=r4[3];
            }
            #pragma unroll
            for (int mt=0;mt<4;mt++)
                #pragma unroll
                for (int nt=0;nt<4;nt++)
                    mma_f16(acc[mt][nt], ah[mt], bh[nt]);
        }
        if (kb+2 < 16) issue((kb+2)%3, (kb+2)*64);
    }

    #pragma unroll
    for (int mt=0;mt<4;mt++){
        #pragma unroll
        for (int nt=0;nt<4;nt++){
            int r = m0 + wm*64 + mt*16 + g;
            int c = n0 + wn*32 + nt*8 + 2*tig;
            float v00 = acc[mt][nt][0] + bias[c];
            float v01 = acc[mt][nt][1] + bias[c+1];
            float v10 = acc[mt][nt][2] + bias[c];
            float v11 = acc[mt][nt][3] + bias[c+1];
            if (mode == 0){
                *(float2*)(outf + (size_t)r*1024 + c)      = make_float2(v00, v01);
                *(float2*)(outf + (size_t)(r+8)*1024 + c)  = make_float2(v10, v11);
            } else {
                int n2 = c, half = 0;
                if (mode == 2 && c >= 1024){ n2 = c - 1024; half = 1; }
                int h = n2>>6, hd = n2&63;
                #pragma unroll
                for (int rr=0; rr<2; rr++){
                    int m = r + rr*8;
                    int b = m>>11, l = m&2047;
                    float a0 = rr?v10:v00, a1 = rr?v11:v01;
                    size_t base = ((size_t)(b*16 + h)*2048 + l)*64 + hd;
                    if (mode == 1)      *(unsigned*)(g_Qh  + base) = pkh(a0*0.125f, a1*0.125f);
                    else if (!half)     *(unsigned*)(g_Kch + base) = pkh(a0, a1);
                    else                *(unsigned*)(g_Vh  + base) = pkh(a0, a1);
                }
            }
        }
    }
}

// persistent fused Q + KV projection; tiles: 24 x-tiles (8 Q + 16 KV) x 32 m-tiles
#define QKV_TILES (24*32)
__global__ __launch_bounds__(256,2) void hqkv(
    const hf* __restrict__ xh, const hf* __restrict__ chp,
    const hf* __restrict__ wq, const hf* __restrict__ wk,
    const float* __restrict__ bq, const float* __restrict__ bkv)
{
    extern __shared__ hf gsm[];
    __shared__ int s_t;
    for (;;){
        __syncthreads();                       // protect s_t and smem stages
        if (threadIdx.x == 0) s_t = atomicAdd(&g_tilec, 1);
        __syncthreads();
        int t = s_t;
        if (t >= QKV_TILES) return;
        int bx = t % 24, m0 = (t / 24) * 128;
        if (bx < 8){
            gemm_body(xh, wq, bq, 1, nullptr, m0, bx*128, gsm);
        } else {
            if ((m0 & 2047) >= g_nv[m0 >> 11]) continue;
            gemm_body(chp, wk, bkv, 2, nullptr, m0, (bx-8)*128, gsm);
        }
    }
}
// output projection (grid 8x32 = 256 CTAs < 1 wave; no queue needed)
__global__ __launch_bounds__(256,2) void hproj(
    const hf* __restrict__ oh, const hf* __restrict__ wp,
    const float* __restrict__ bp, float* __restrict__ outf)
{
    extern __shared__ hf gsm[];
    gemm_body(oh, wp, bp, 0, outf, blockIdx.y*128, blockIdx.x*128, gsm);
}

// ---------------- HMMA flash attention (fp16, V via ldmatrix.trans) ----------------
#define ALD 72
#define QH_O 0
#define STG0 (64*ALD)
#define A_STG (2*64*ALD)
#define SM_ELEMS (STG0 + 2*A_STG)
#define ATT_SMEM (SM_ELEMS*2)

__global__ __launch_bounds__(128) void hattn()
{
    extern __shared__ hf sm[];
    const uint32_t sbase = smem_u32(sm);
    const int tid = threadIdx.x, lane = tid&31, warp = tid>>5;
    const int g = lane>>2, tig = lane&3;
    const int bh = blockIdx.y, b = bh>>4, h = bh&15, l0 = blockIdx.x*64;
    const int lrow = lane&7, ltile = lane>>3;
    const int rowA = (ltile&1)*8 + lrow, kA = (ltile>>1)*8;
    const int rowB = (ltile>>1)*8 + lrow, kB = (ltile&1)*8;
    const int nv = g_nv[b];
    const int nch = (nv + 63) >> 6;

    auto issueKV = [&](int buf, int t0){
        #pragma unroll
        for (int t=0;t<8;t++){
            int i = tid + t*128, plane = i>>9, w = i&511, row = w>>3, c8 = (w&7)*8;
            const hf* gp = (plane == 0)
                ? g_Kch + ((size_t)bh*Tv + t0 + row)*64 + c8
                : g_Vh  + ((size_t)bh*Tv + t0 + row)*64 + c8;
            cp16(sbase + (uint32_t)(STG0 + buf*A_STG + plane*(64*ALD) + row*ALD + c8)*2, gp);
        }
        CP_COMMIT();
    };

    #pragma unroll
    for (int t=0;t<4;t++){
        int i = tid + t*128, row = i>>3, c8 = (i&7)*8;
        uint4 v = *(const uint4*)(g_Qh + ((size_t)bh*Lv + l0 + row)*64 + c8);
        *(uint4*)(sm + QH_O + row*ALD + c8) = v;
    }
    issueKV(0, 0);
    __syncthreads();

    unsigned qa[4][4];
    #pragma unroll
    for (int kk=0; kk<4; kk++)
        ldsm4(qa[kk], sbase + (uint32_t)(QH_O + (warp*16 + rowA)*ALD + kk*16 + kA)*2);

    float mold[2] = {-INFINITY, -INFINITY};
    float lsum[2] = {0.f, 0.f};
    float o[8][4] = {};

    for (int ci=0; ci<nch; ci++){
        const int t0 = ci*64;
        if (ci < nch-1) issueKV((ci+1)&1, t0+64);
        if (ci < nch-1) CP_WAIT1(); else CP_WAIT0();
        __syncthreads();

        const uint32_t khB = sbase + (uint32_t)(STG0 + (ci&1)*A_STG)*2;
        const uint32_t vhB = khB + 64*ALD*2;
        const int rem = nv - t0;

        float s[8][4] = {};
        #pragma unroll
        for (int kk=0; kk<4; kk++){
            unsigned bhf[8][2];
            #pragma unroll
            for (int p2=0; p2<4; p2++){
                unsigned r4[4];
                uint32_t off = (uint32_t)((p2*16 + rowB)*ALD + kk*16 + kB)*2;
                ldsm4(r4, khB + off);
                bhf[2*p2][0]=r4[0]; bhf[2*p2][1]=r4[1]; bhf[2*p2+1][0]=r4[2]; bhf[2*p2+1][1]=r4[3];
            }
            #pragma unroll
            for (int nt=0; nt<8; nt++)
                mma_f16(s[nt], qa[kk], bhf[nt]);
        }

        float ma = mold[0], mb = mold[1];
        #pragma unroll
        for (int nt=0; nt<8; nt++){
            int c = nt*8 + 2*tig;
            if (c   >= rem){ s[nt][0] = -1e9f; s[nt][2] = -1e9f; }
            if (c+1 >= rem){ s[nt][1] = -1e9f; s[nt][3] = -1e9f; }
            ma = fmaxf(ma, fmaxf(s[nt][0], s[nt][1]));
            mb = fmaxf(mb, fmaxf(s[nt][2], s[nt][3]));
        }
        ma = fmaxf(ma, __shfl_xor_sync(0xffffffffu, ma, 1));
        ma = fmaxf(ma, __shfl_xor_sync(0xffffffffu, ma, 2));
        mb = fmaxf(mb, __shfl_xor_sync(0xffffffffu, mb, 1));
        mb = fmaxf(mb, __shfl_xor_sync(0xffffffffu, mb, 2));

        float aa = __expf(mold[0] - ma), ab = __expf(mold[1] - mb);
        float suma = 0.f, sumb = 0.f;
        #pragma unroll
        for (int nt=0; nt<8; nt++){
            s[nt][0] = __expf(s[nt][0] - ma);
            s[nt][1] = __expf(s[nt][1] - ma);
            s[nt][2] = __expf(s[nt][2] - mb);
            s[nt][3] = __expf(s[nt][3] - mb);
            suma += s[nt][0] + s[nt][1];
            sumb += s[nt][2] + s[nt][3];
        }
        suma += __shfl_xor_sync(0xffffffffu, suma, 1);
        suma += __shfl_xor_sync(0xffffffffu, suma, 2);
        sumb += __shfl_xor_sync(0xffffffffu, sumb, 1);
        sumb += __shfl_xor_sync(0xffffffffu, sumb, 2);
        lsum[0] = lsum[0]*aa + suma;  mold[0] = ma;
        lsum[1] = lsum[1]*ab + sumb;  mold[1] = mb;
        #pragma unroll
        for (int nt=0; nt<8; nt++){
            o[nt][0] *= aa; o[nt][1] *= aa; o[nt][2] *= ab; o[nt][3] *= ab;
        }

        #pragma unroll
        for (int kt=0; kt<4; kt++){
            unsigned pa[4];
            pa[0] = pkh(s[2*kt][0],   s[2*kt][1]);
            pa[1] = pkh(s[2*kt][2],   s[2*kt][3]);
            pa[2] = pkh(s[2*kt+1][0], s[2*kt+1][1]);
            pa[3] = pkh(s[2*kt+1][2], s[2*kt+1][3]);
            #pragma unroll
            for (int p2=0; p2<4; p2++){
                unsigned rv[4];
                uint32_t off = (uint32_t)((kt*16 + rowA)*ALD + p2*16 + kA)*2;
                ldsm4t(rv, vhB + off);
                unsigned v0[2] = {rv[0], rv[1]}, v1[2] = {rv[2], rv[3]};
                mma_f16(o[2*p2],   pa, v0);
                mma_f16(o[2*p2+1], pa, v1);
            }
        }
        __syncthreads();
    }

    float inva = 1.0f / lsum[0], invb = 1.0f / lsum[1];
    int ra = l0 + warp*16 + g, rb = ra + 8;
    #pragma unroll
    for (int nt=0; nt<8; nt++){
        int c = h*64 + nt*8 + 2*tig;
        *(unsigned*)(g_Oh + ((size_t)(b*Lv + ra))*Dv + c) = pkh(o[nt][0]*inva, o[nt][1]*inva);
        *(unsigned*)(g_Oh + ((size_t)(b*Lv + rb))*Dv + c) = pkh(o[nt][2]*invb, o[nt][3]*invb);
    }
}

// ---------------- launch ----------------
extern "C" void kernel_launch(void* const* d_in, const int* in_sizes, int n_in,
                              void* d_out, int out_size)
{
    const float* x     = (const float*)d_in[0];
    const float* ctx   = (const float*)d_in[1];
    const int*   cmsk  = (const int*)d_in[2];
    const float* Wq    = (const float*)d_in[3];
    const float* bq    = (const float*)d_in[4];
    const float* Wkv   = (const float*)d_in[5];
    const float* bkv   = (const float*)d_in[6];
    const float* Wproj = (const float*)d_in[7];
    const float* bproj = (const float*)d_in[8];
    float* out         = (float*)d_out;

    hf *xh,*ch,*wqh,*wkh,*wph,*oh;
    cudaGetSymbolAddress((void**)&xh, g_xh);
    cudaGetSymbolAddress((void**)&ch, g_ch);
    cudaGetSymbolAddress((void**)&wqh, g_Wqh);
    cudaGetSymbolAddress((void**)&wkh, g_Wkh);
    cudaGetSymbolAddress((void**)&wph, g_Wph);
    cudaGetSymbolAddress((void**)&oh, g_Oh);

    cudaFuncSetAttribute(hqkv,  cudaFuncAttributeMaxDynamicSharedMemorySize, G_SMEM_BYTES);
    cudaFuncSetAttribute(hproj, cudaFuncAttributeMaxDynamicSharedMemorySize, G_SMEM_BYTES);
    cudaFuncSetAttribute(hattn, cudaFuncAttributeMaxDynamicSharedMemorySize, ATT_SMEM);

    const int NM = Bv*Lv;  // 4096

    mscan<<<Bv, 256>>>(cmsk);                                            // 0 (+ counter reset)
    prep_all<<<2*NM + 4096, 256>>>(x, ctx, Wq, Wkv, Wproj);              // 1
    hqkv<<<296, 256, G_SMEM_BYTES>>>(xh, ch, wqh, wkh, bq, bkv);         // 2 (persistent)
    hattn<<<dim3(Lv/64, BHv), 128, ATT_SMEM>>>();                        // 3 (ncu slot)
    hproj<<<dim3(Dv/128, NM/128), 256, G_SMEM_BYTES>>>(oh, wph, bproj, out);  // 4
}